// round 2
// baseline (speedup 1.0000x reference)
#include <cuda_runtime.h>

#define NPTS   131072
#define GL     5
#define FD     8
#define WD     256
#define OD     64
#define MTILE  128
#define NTHR   256
#define KB     16
#define XSTR   132              /* 128 + 4 pad floats, keeps 16B alignment */
#define NBLK   (WD/KB)          /* 16 */

typedef unsigned long long u64;

__device__ __forceinline__ u64 pack2(float lo, float hi) {
    u64 r; asm("mov.b64 %0, {%1, %2};" : "=l"(r) : "f"(lo), "f"(hi)); return r;
}
__device__ __forceinline__ void unpack2(u64 v, float& lo, float& hi) {
    asm("mov.b64 {%0, %1}, %2;" : "=f"(lo), "=f"(hi) : "l"(v));
}
__device__ __forceinline__ void ffma2(u64& d, u64 a, u64 b) {
    asm("fma.rn.f32x2 %0, %1, %2, %0;" : "+l"(d) : "l"(a), "l"(b));
}

/* shared memory layout (floats) */
#define OFF_XT    0
#define SZ_XT     (WD*XSTR)          /* 33792 */
#define OFF_WBUF  (OFF_XT+SZ_XT)
#define SZ_WBUF   (2*KB*WD)          /* 8192  */
#define OFF_GF    (OFF_WBUF+SZ_WBUF)
#define SZ_GF     (MTILE*GL*FD)      /* 5120  */
#define OFF_FFN   (OFF_GF+SZ_GF)
#define SZ_FFN    (FD*WD)            /* 2048  */
#define OFF_BS    (OFF_FFN+SZ_FFN)
#define SZ_BS     (WD)
#define OFF_BH    (OFF_BS+SZ_BS)
#define SZ_BH     (OD)
#define OFF_POS   (OFF_BH+SZ_BH)
#define SZ_POS    (MTILE*3)
#define SMEM_FLOATS (OFF_POS+SZ_POS)
#define SMEM_BYTES  (SMEM_FLOATS*4)  /* 199424 B */

__global__ void __launch_bounds__(NTHR, 1)
ffb_kernel(const float* __restrict__ pos,
           const float* __restrict__ gf,
           const float* __restrict__ ffnA,
           const float* __restrict__ w0,
           const float* __restrict__ b0,
           const float* __restrict__ wh,
           const float* __restrict__ bhv,
           const float* __restrict__ whh,
           const float* __restrict__ bhh,
           float* __restrict__ outp)
{
    extern __shared__ float sm[];
    float* xT   = sm + OFF_XT;    /* x transposed: xT[k][m], k<256, m<128 */
    float* wbuf = sm + OFF_WBUF;  /* double-buffered weight k-blocks      */
    float* gfb  = sm + OFF_GF;    /* grid feats tile [128][40]            */
    float* ffnS = sm + OFF_FFN;   /* scaled fourier weights [8][256]      */
    float* bsm  = sm + OFF_BS;    /* bias [256]                           */
    float* bhsm = sm + OFF_BH;    /* head bias [64]                       */
    float* posb = sm + OFF_POS;   /* positions [128][3]                   */

    const int tid = threadIdx.x;
    const int tx  = tid & 15;          /* n-dim thread coord */
    const int ty  = tid >> 4;          /* m-dim thread coord */
    const int m0  = ty << 3;
    const long base = (long)blockIdx.x * MTILE;

    /* ---- stage per-tile inputs ---- */
    for (int i = tid; i < MTILE*GL*FD; i += NTHR) gfb[i]  = gf[base*(GL*FD) + i];
    for (int i = tid; i < MTILE*3;     i += NTHR) posb[i] = pos[base*3 + i];
    for (int i = tid; i < 3*WD;        i += NTHR) wbuf[i] = w0[i];
    for (int i = tid; i < WD;          i += NTHR) bsm[i]  = b0[i];
    __syncthreads();

    /* ---- layer 0: x = sin(5*(pos @ W0 + b0)), K=3 ---- */
    #pragma unroll
    for (int mi = 0; mi < 8; ++mi) {
        int m = m0 + mi;
        float p0 = posb[m*3], p1 = posb[m*3+1], p2 = posb[m*3+2];
        #pragma unroll
        for (int j = 0; j < 4; ++j) {
            int n = (j<<6) + (tx<<2);
            #pragma unroll
            for (int q = 0; q < 4; ++q) {
                float h = bsm[n+q];
                h = fmaf(p0, wbuf[      n+q], h);
                h = fmaf(p1, wbuf[WD  + n+q], h);
                h = fmaf(p2, wbuf[2*WD+ n+q], h);
                xT[(n+q)*XSTR + m] = __sinf(5.0f*h);
            }
        }
    }

    float oacc[8][4];
    #pragma unroll
    for (int mi = 0; mi < 8; ++mi)
        #pragma unroll
        for (int q = 0; q < 4; ++q) oacc[mi][q] = 0.f;

    for (int l = 0; l < GL; ++l) {
        __syncthreads();   /* guards bsm/bhsm/ffnS/wbuf rewrite + layer-0 xT writes */

        /* ---- stage level constants + first weight block ---- */
        const float gs = 6.283185307179586f * (float)(1 << l);  /* 2*pi*sigma_l */
        for (int i = tid; i < FD*WD; i += NTHR) ffnS[i] = ffnA[l*FD*WD + i] * gs;
        for (int i = tid; i < WD;    i += NTHR) bsm[i]  = bhv[l*WD + i];
        for (int i = tid; i < OD;    i += NTHR) bhsm[i] = bhh[l*OD + i];
        const float* wl = wh + (long)l*WD*WD;
        {
            const float4* src = (const float4*)wl;
            float4* dst = (float4*)wbuf;
            #pragma unroll
            for (int i = 0; i < 4; ++i) dst[i*NTHR + tid] = src[i*NTHR + tid];
        }
        __syncthreads();

        /* ---- main GEMM: h = x @ Wh[l]  (M=128,N=256,K=256) ---- */
        u64 acc[8][8];   /* 8 m-rows x 8 n-pairs, f32x2 accumulators */
        #pragma unroll
        for (int mi = 0; mi < 8; ++mi)
            #pragma unroll
            for (int jp = 0; jp < 8; ++jp) acc[mi][jp] = 0ULL;

        for (int blk = 0; blk < NBLK; ++blk) {
            float4 nxt[4];
            const int cur = blk & 1;
            if (blk + 1 < NBLK) {
                const float4* src = (const float4*)(wl + (blk+1)*KB*WD);
                #pragma unroll
                for (int i = 0; i < 4; ++i) nxt[i] = src[i*NTHR + tid];
            }
            const float* wb = wbuf + cur*(KB*WD);
            #pragma unroll
            for (int kk = 0; kk < KB; ++kk) {
                const int k = blk*KB + kk;
                const float* xr = xT + k*XSTR + m0;
                float4 x0 = *(const float4*)xr;
                float4 x1 = *(const float4*)(xr + 4);
                u64 xa[8];
                xa[0]=pack2(x0.x,x0.x); xa[1]=pack2(x0.y,x0.y);
                xa[2]=pack2(x0.z,x0.z); xa[3]=pack2(x0.w,x0.w);
                xa[4]=pack2(x1.x,x1.x); xa[5]=pack2(x1.y,x1.y);
                xa[6]=pack2(x1.z,x1.z); xa[7]=pack2(x1.w,x1.w);
                const float* wr = wb + kk*WD + (tx<<2);
                #pragma unroll
                for (int j = 0; j < 4; ++j) {
                    ulonglong2 wp = *(const ulonglong2*)(wr + (j<<6));
                    #pragma unroll
                    for (int mi = 0; mi < 8; ++mi) {
                        ffma2(acc[mi][2*j  ], xa[mi], wp.x);
                        ffma2(acc[mi][2*j+1], xa[mi], wp.y);
                    }
                }
            }
            if (blk + 1 < NBLK) {
                float4* dst = (float4*)(wbuf + (cur^1)*(KB*WD));
                #pragma unroll
                for (int i = 0; i < 4; ++i) dst[i*NTHR + tid] = nxt[i];
            }
            __syncthreads();
        }

        /* ---- epilogue: x_new = sin(5*(h+bh)) + sin(gf @ ffnS) ---- */
        #pragma unroll
        for (int mi = 0; mi < 8; ++mi) {
            const int m = m0 + mi;
            const float* gfr = gfb + m*(GL*FD) + l*FD;
            float4 gq0 = *(const float4*)gfr;
            float4 gq1 = *(const float4*)(gfr + 4);
            float gv[8] = {gq0.x,gq0.y,gq0.z,gq0.w,gq1.x,gq1.y,gq1.z,gq1.w};
            u64 g[8];
            #pragma unroll
            for (int jp = 0; jp < 8; ++jp) g[jp] = 0ULL;
            #pragma unroll
            for (int f = 0; f < FD; ++f) {
                u64 ga = pack2(gv[f], gv[f]);
                const float* fr = ffnS + f*WD + (tx<<2);
                #pragma unroll
                for (int j = 0; j < 4; ++j) {
                    ulonglong2 fp = *(const ulonglong2*)(fr + (j<<6));
                    ffma2(g[2*j  ], ga, fp.x);
                    ffma2(g[2*j+1], ga, fp.y);
                }
            }
            #pragma unroll
            for (int j = 0; j < 4; ++j) {
                int n = (j<<6) + (tx<<2);
                float h0,h1,h2,h3,q0,q1,q2,q3;
                unpack2(acc[mi][2*j  ], h0, h1);
                unpack2(acc[mi][2*j+1], h2, h3);
                unpack2(g[2*j  ], q0, q1);
                unpack2(g[2*j+1], q2, q3);
                float v0 = __sinf(5.f*(h0+bsm[n  ])) + __sinf(q0);
                float v1 = __sinf(5.f*(h1+bsm[n+1])) + __sinf(q1);
                float v2 = __sinf(5.f*(h2+bsm[n+2])) + __sinf(q2);
                float v3 = __sinf(5.f*(h3+bsm[n+3])) + __sinf(q3);
                acc[mi][2*j  ] = pack2(v0, v1);
                acc[mi][2*j+1] = pack2(v2, v3);
            }
        }
        /* write x_new back transposed (all GEMM reads completed at last sync) */
        #pragma unroll
        for (int j = 0; j < 4; ++j) {
            #pragma unroll
            for (int p = 0; p < 4; ++p) {
                int n = (j<<6) + (tx<<2) + p;
                float c[8];
                #pragma unroll
                for (int mi = 0; mi < 8; ++mi) {
                    float lo, hi;
                    unpack2(acc[mi][2*j + (p>>1)], lo, hi);
                    c[mi] = (p & 1) ? hi : lo;
                }
                float* xw = xT + n*XSTR + m0;
                *(float4*)xw       = make_float4(c[0],c[1],c[2],c[3]);
                *(float4*)(xw + 4) = make_float4(c[4],c[5],c[6],c[7]);
            }
        }
        __syncthreads();

        /* ---- head GEMM: out += sin(5*(x_new @ Whh[l] + bhh))  (N=64) ---- */
        const float* whl = whh + (long)l*WD*OD;
        {
            const float4* src = (const float4*)whl;
            float4* dst = (float4*)wbuf;
            #pragma unroll
            for (int i = 0; i < 4; ++i) dst[i*NTHR + tid] = src[i*NTHR + tid];
        }
        __syncthreads();

        u64 acc2[4][4];   /* 4 m-pairs x 4 o-columns */
        #pragma unroll
        for (int mp = 0; mp < 4; ++mp)
            #pragma unroll
            for (int q = 0; q < 4; ++q) acc2[mp][q] = 0ULL;

        for (int blk = 0; blk < 4; ++blk) {    /* 64 k per block */
            float4 nxt[4];
            const int cur = blk & 1;
            if (blk + 1 < 4) {
                const float4* src = (const float4*)(whl + (blk+1)*64*OD);
                #pragma unroll
                for (int i = 0; i < 4; ++i) nxt[i] = src[i*NTHR + tid];
            }
            const float* wb = wbuf + cur*(KB*WD);
            #pragma unroll 8
            for (int kk = 0; kk < 64; ++kk) {
                const int k = blk*64 + kk;
                const float* xr = xT + k*XSTR + m0;
                ulonglong2 xp0 = *(const ulonglong2*)xr;        /* natural m-pairs */
                ulonglong2 xp1 = *(const ulonglong2*)(xr + 4);
                const float* wrr = wb + kk*OD + (tx<<2);
                float4 wv = *(const float4*)wrr;
                u64 wd0 = pack2(wv.x, wv.x);
                u64 wd1 = pack2(wv.y, wv.y);
                u64 wd2 = pack2(wv.z, wv.z);
                u64 wd3 = pack2(wv.w, wv.w);
                ffma2(acc2[0][0], xp0.x, wd0); ffma2(acc2[0][1], xp0.x, wd1);
                ffma2(acc2[0][2], xp0.x, wd2); ffma2(acc2[0][3], xp0.x, wd3);
                ffma2(acc2[1][0], xp0.y, wd0); ffma2(acc2[1][1], xp0.y, wd1);
                ffma2(acc2[1][2], xp0.y, wd2); ffma2(acc2[1][3], xp0.y, wd3);
                ffma2(acc2[2][0], xp1.x, wd0); ffma2(acc2[2][1], xp1.x, wd1);
                ffma2(acc2[2][2], xp1.x, wd2); ffma2(acc2[2][3], xp1.x, wd3);
                ffma2(acc2[3][0], xp1.y, wd0); ffma2(acc2[3][1], xp1.y, wd1);
                ffma2(acc2[3][2], xp1.y, wd2); ffma2(acc2[3][3], xp1.y, wd3);
            }
            if (blk + 1 < 4) {
                float4* dst = (float4*)(wbuf + (cur^1)*(KB*WD));
                #pragma unroll
                for (int i = 0; i < 4; ++i) dst[i*NTHR + tid] = nxt[i];
            }
            __syncthreads();
        }

        const int o = tx << 2;
        const float bo0 = bhsm[o], bo1 = bhsm[o+1], bo2 = bhsm[o+2], bo3 = bhsm[o+3];
        #pragma unroll
        for (int mp = 0; mp < 4; ++mp) {
            float e0, e1;
            unpack2(acc2[mp][0], e0, e1);
            oacc[2*mp][0]   += __sinf(5.f*(e0+bo0));
            oacc[2*mp+1][0] += __sinf(5.f*(e1+bo0));
            unpack2(acc2[mp][1], e0, e1);
            oacc[2*mp][1]   += __sinf(5.f*(e0+bo1));
            oacc[2*mp+1][1] += __sinf(5.f*(e1+bo1));
            unpack2(acc2[mp][2], e0, e1);
            oacc[2*mp][2]   += __sinf(5.f*(e0+bo2));
            oacc[2*mp+1][2] += __sinf(5.f*(e1+bo2));
            unpack2(acc2[mp][3], e0, e1);
            oacc[2*mp][3]   += __sinf(5.f*(e0+bo3));
            oacc[2*mp+1][3] += __sinf(5.f*(e1+bo3));
        }
    }

    /* ---- write output tile ---- */
    #pragma unroll
    for (int mi = 0; mi < 8; ++mi) {
        long row = base + m0 + mi;
        *(float4*)(outp + row*(long)OD + (tx<<2)) =
            make_float4(oacc[mi][0], oacc[mi][1], oacc[mi][2], oacc[mi][3]);
    }
}

extern "C" void kernel_launch(void* const* d_in, const int* in_sizes, int n_in,
                              void* d_out, int out_size) {
    /* map inputs by element count (all sizes are distinct) */
    const float *pos=0,*gfp=0,*ffn=0,*w0=0,*b0=0,*wh=0,*bh=0,*whh=0,*bhh=0;
    for (int i = 0; i < n_in; ++i) {
        const float* p = (const float*)d_in[i];
        switch (in_sizes[i]) {
            case NPTS*3:        pos = p; break;   /* in_pos     */
            case NPTS*GL*FD:    gfp = p; break;   /* grid_feats */
            case GL*FD*WD:      ffn = p; break;   /* ffn_A      */
            case 3*WD:          w0  = p; break;   /* W0         */
            case WD:            b0  = p; break;   /* b0         */
            case GL*WD*WD:      wh  = p; break;   /* Wh         */
            case GL*WD:         bh  = p; break;   /* bh         */
            case GL*WD*OD:      whh = p; break;   /* Wh_high    */
            case GL*OD:         bhh = p; break;   /* bh_high    */
        }
    }
    cudaFuncSetAttribute(ffb_kernel, cudaFuncAttributeMaxDynamicSharedMemorySize, SMEM_BYTES);
    ffb_kernel<<<NPTS/MTILE, NTHR, SMEM_BYTES>>>(pos, gfp, ffn, w0, b0,
                                                 wh, bh, whh, bhh, (float*)d_out);
}

// round 3
// speedup vs baseline: 1.0547x; 1.0547x over previous
#include <cuda_runtime.h>

#define NPTS   131072
#define GL     5
#define FD     8
#define WD     256
#define OD     64
#define MTILE  128
#define NTHR   256
#define KB     16
#define XSTR   132              /* 128 + 4 pad floats, keeps 16B alignment */
#define NBLK   (WD/KB)          /* 16 */

typedef unsigned long long u64;

__device__ __forceinline__ u64 pack2(float lo, float hi) {
    u64 r; asm("mov.b64 %0, {%1, %2};" : "=l"(r) : "f"(lo), "f"(hi)); return r;
}
__device__ __forceinline__ void unpack2(u64 v, float& lo, float& hi) {
    asm("mov.b64 {%0, %1}, %2;" : "=f"(lo), "=f"(hi) : "l"(v));
}
__device__ __forceinline__ void ffma2(u64& d, u64 a, u64 b) {
    asm("fma.rn.f32x2 %0, %1, %2, %0;" : "+l"(d) : "l"(a), "l"(b));
}

/* shared memory layout (floats) */
#define OFF_XT    0
#define SZ_XT     (WD*XSTR)          /* 33792 */
#define OFF_WBUF  (OFF_XT+SZ_XT)
#define SZ_WBUF   (2*KB*WD)          /* 8192  */
#define OFF_GF    (OFF_WBUF+SZ_WBUF)
#define SZ_GF     (MTILE*GL*FD)      /* 5120  */
#define OFF_FFN   (OFF_GF+SZ_GF)
#define SZ_FFN    (FD*WD)            /* 2048  */
#define OFF_BS    (OFF_FFN+SZ_FFN)
#define SZ_BS     (WD)
#define OFF_BH    (OFF_BS+SZ_BS)
#define SZ_BH     (OD)
#define OFF_POS   (OFF_BH+SZ_BH)
#define SZ_POS    (MTILE*3)
#define SMEM_FLOATS (OFF_POS+SZ_POS)
#define SMEM_BYTES  (SMEM_FLOATS*4)  /* 199424 B */

__global__ void __launch_bounds__(NTHR, 1)
ffb_kernel(const float* __restrict__ pos,
           const float* __restrict__ gf,
           const float* __restrict__ ffnA,
           const float* __restrict__ w0,
           const float* __restrict__ b0,
           const float* __restrict__ wh,
           const float* __restrict__ bhv,
           const float* __restrict__ whh,
           const float* __restrict__ bhh,
           float* __restrict__ outp)
{
    extern __shared__ float sm[];
    float* xT   = sm + OFF_XT;    /* x transposed: xT[k][m], k<256, m<128 */
    float* wbuf = sm + OFF_WBUF;  /* double-buffered weight k-blocks      */
    float* gfb  = sm + OFF_GF;    /* grid feats tile [128][40]            */
    float* ffnS = sm + OFF_FFN;   /* scaled fourier weights [8][256]      */
    float* bsm  = sm + OFF_BS;    /* bias [256]                           */
    float* bhsm = sm + OFF_BH;    /* head bias [64]                       */
    float* posb = sm + OFF_POS;   /* positions [128][3]                   */

    const int tid = threadIdx.x;
    const int tx  = tid & 15;          /* n-dim thread coord */
    const int ty  = tid >> 4;          /* m-dim thread coord */
    const int m0  = ty << 3;
    const long base = (long)blockIdx.x * MTILE;

    /* ---- stage per-tile inputs ---- */
    for (int i = tid; i < MTILE*GL*FD; i += NTHR) gfb[i]  = gf[base*(GL*FD) + i];
    for (int i = tid; i < MTILE*3;     i += NTHR) posb[i] = pos[base*3 + i];
    for (int i = tid; i < 3*WD;        i += NTHR) wbuf[i] = w0[i];
    for (int i = tid; i < WD;          i += NTHR) bsm[i]  = b0[i];
    __syncthreads();

    /* ---- layer 0: x = sin(5*(pos @ W0 + b0)), K=3 ---- */
    #pragma unroll
    for (int mi = 0; mi < 8; ++mi) {
        int m = m0 + mi;
        float p0 = posb[m*3], p1 = posb[m*3+1], p2 = posb[m*3+2];
        #pragma unroll
        for (int j = 0; j < 4; ++j) {
            int n = (j<<6) + (tx<<2);
            #pragma unroll
            for (int q = 0; q < 4; ++q) {
                float h = bsm[n+q];
                h = fmaf(p0, wbuf[      n+q], h);
                h = fmaf(p1, wbuf[WD  + n+q], h);
                h = fmaf(p2, wbuf[2*WD+ n+q], h);
                xT[(n+q)*XSTR + m] = __sinf(5.0f*h);
            }
        }
    }

    float oacc[8][4];
    #pragma unroll
    for (int mi = 0; mi < 8; ++mi)
        #pragma unroll
        for (int q = 0; q < 4; ++q) oacc[mi][q] = 0.f;

    for (int l = 0; l < GL; ++l) {
        __syncthreads();   /* guards bsm/bhsm/ffnS/wbuf rewrite + layer-0 xT writes */

        /* ---- stage level constants + first weight block ---- */
        const float gs = 6.283185307179586f * (float)(1 << l);  /* 2*pi*sigma_l */
        for (int i = tid; i < FD*WD; i += NTHR) ffnS[i] = ffnA[l*FD*WD + i] * gs;
        for (int i = tid; i < WD;    i += NTHR) bsm[i]  = bhv[l*WD + i];
        for (int i = tid; i < OD;    i += NTHR) bhsm[i] = bhh[l*OD + i];
        const float* wl = wh + (long)l*WD*WD;
        {
            const float4* src = (const float4*)wl;
            float4* dst = (float4*)wbuf;
            #pragma unroll
            for (int i = 0; i < 4; ++i) dst[i*NTHR + tid] = src[i*NTHR + tid];
        }
        __syncthreads();

        /* ---- main GEMM: h = x @ Wh[l]  (M=128,N=256,K=256) ---- */
        u64 acc[8][8];   /* 8 m-rows x 8 n-pairs, f32x2 accumulators */
        #pragma unroll
        for (int mi = 0; mi < 8; ++mi)
            #pragma unroll
            for (int jp = 0; jp < 8; ++jp) acc[mi][jp] = 0ULL;

        for (int blk = 0; blk < NBLK; ++blk) {
            float4 nxt[4];
            const int cur = blk & 1;
            if (blk + 1 < NBLK) {
                const float4* src = (const float4*)(wl + (blk+1)*KB*WD);
                #pragma unroll
                for (int i = 0; i < 4; ++i) nxt[i] = src[i*NTHR + tid];
            }
            const float* wb = wbuf + cur*(KB*WD);
            #pragma unroll
            for (int kk = 0; kk < KB; ++kk) {
                const int k = blk*KB + kk;
                const float* xr = xT + k*XSTR + m0;
                float4 x0 = *(const float4*)xr;
                float4 x1 = *(const float4*)(xr + 4);
                u64 xa[8];
                xa[0]=pack2(x0.x,x0.x); xa[1]=pack2(x0.y,x0.y);
                xa[2]=pack2(x0.z,x0.z); xa[3]=pack2(x0.w,x0.w);
                xa[4]=pack2(x1.x,x1.x); xa[5]=pack2(x1.y,x1.y);
                xa[6]=pack2(x1.z,x1.z); xa[7]=pack2(x1.w,x1.w);
                const float* wr = wb + kk*WD + (tx<<2);
                #pragma unroll
                for (int j = 0; j < 4; ++j) {
                    ulonglong2 wp = *(const ulonglong2*)(wr + (j<<6));
                    #pragma unroll
                    for (int mi = 0; mi < 8; ++mi) {
                        ffma2(acc[mi][2*j  ], xa[mi], wp.x);
                        ffma2(acc[mi][2*j+1], xa[mi], wp.y);
                    }
                }
            }
            if (blk + 1 < NBLK) {
                float4* dst = (float4*)(wbuf + (cur^1)*(KB*WD));
                #pragma unroll
                for (int i = 0; i < 4; ++i) dst[i*NTHR + tid] = nxt[i];
            }
            __syncthreads();
        }

        /* ---- epilogue: x_new = sin(5*(h+bh)) + sin(gf @ ffnS) ---- */
        #pragma unroll
        for (int mi = 0; mi < 8; ++mi) {
            const int m = m0 + mi;
            const float* gfr = gfb + m*(GL*FD) + l*FD;
            float4 gq0 = *(const float4*)gfr;
            float4 gq1 = *(const float4*)(gfr + 4);
            float gv[8] = {gq0.x,gq0.y,gq0.z,gq0.w,gq1.x,gq1.y,gq1.z,gq1.w};
            u64 g[8];
            #pragma unroll
            for (int jp = 0; jp < 8; ++jp) g[jp] = 0ULL;
            #pragma unroll
            for (int f = 0; f < FD; ++f) {
                u64 ga = pack2(gv[f], gv[f]);
                const float* fr = ffnS + f*WD + (tx<<2);
                #pragma unroll
                for (int j = 0; j < 4; ++j) {
                    ulonglong2 fp = *(const ulonglong2*)(fr + (j<<6));
                    ffma2(g[2*j  ], ga, fp.x);
                    ffma2(g[2*j+1], ga, fp.y);
                }
            }
            #pragma unroll
            for (int j = 0; j < 4; ++j) {
                int n = (j<<6) + (tx<<2);
                float h0,h1,h2,h3,q0,q1,q2,q3;
                unpack2(acc[mi][2*j  ], h0, h1);
                unpack2(acc[mi][2*j+1], h2, h3);
                unpack2(g[2*j  ], q0, q1);
                unpack2(g[2*j+1], q2, q3);
                float v0 = __sinf(5.f*(h0+bsm[n  ])) + __sinf(q0);
                float v1 = __sinf(5.f*(h1+bsm[n+1])) + __sinf(q1);
                float v2 = __sinf(5.f*(h2+bsm[n+2])) + __sinf(q2);
                float v3 = __sinf(5.f*(h3+bsm[n+3])) + __sinf(q3);
                acc[mi][2*j  ] = pack2(v0, v1);
                acc[mi][2*j+1] = pack2(v2, v3);
            }
        }
        /* write x_new back transposed (all GEMM reads completed at last sync) */
        #pragma unroll
        for (int j = 0; j < 4; ++j) {
            #pragma unroll
            for (int p = 0; p < 4; ++p) {
                int n = (j<<6) + (tx<<2) + p;
                float c[8];
                #pragma unroll
                for (int mi = 0; mi < 8; ++mi) {
                    float lo, hi;
                    unpack2(acc[mi][2*j + (p>>1)], lo, hi);
                    c[mi] = (p & 1) ? hi : lo;
                }
                float* xw = xT + n*XSTR + m0;
                *(float4*)xw       = make_float4(c[0],c[1],c[2],c[3]);
                *(float4*)(xw + 4) = make_float4(c[4],c[5],c[6],c[7]);
            }
        }
        __syncthreads();

        /* ---- head GEMM: out += sin(5*(x_new @ Whh[l] + bhh))  (N=64) ---- */
        const float* whl = whh + (long)l*WD*OD;
        {
            const float4* src = (const float4*)whl;
            float4* dst = (float4*)wbuf;
            #pragma unroll
            for (int i = 0; i < 4; ++i) dst[i*NTHR + tid] = src[i*NTHR + tid];
        }
        __syncthreads();

        u64 acc2[4][4];   /* 4 m-pairs x 4 o-columns */
        #pragma unroll
        for (int mp = 0; mp < 4; ++mp)
            #pragma unroll
            for (int q = 0; q < 4; ++q) acc2[mp][q] = 0ULL;

        for (int blk = 0; blk < 4; ++blk) {    /* 64 k per block */
            float4 nxt[4];
            const int cur = blk & 1;
            if (blk + 1 < 4) {
                const float4* src = (const float4*)(whl + (blk+1)*64*OD);
                #pragma unroll
                for (int i = 0; i < 4; ++i) nxt[i] = src[i*NTHR + tid];
            }
            const float* wb = wbuf + cur*(KB*WD);
            #pragma unroll 8
            for (int kk = 0; kk < 64; ++kk) {
                const int k = blk*64 + kk;
                const float* xr = xT + k*XSTR + m0;
                ulonglong2 xp0 = *(const ulonglong2*)xr;        /* natural m-pairs */
                ulonglong2 xp1 = *(const ulonglong2*)(xr + 4);
                const float* wrr = wb + kk*OD + (tx<<2);
                float4 wv = *(const float4*)wrr;
                u64 wd0 = pack2(wv.x, wv.x);
                u64 wd1 = pack2(wv.y, wv.y);
                u64 wd2 = pack2(wv.z, wv.z);
                u64 wd3 = pack2(wv.w, wv.w);
                ffma2(acc2[0][0], xp0.x, wd0); ffma2(acc2[0][1], xp0.x, wd1);
                ffma2(acc2[0][2], xp0.x, wd2); ffma2(acc2[0][3], xp0.x, wd3);
                ffma2(acc2[1][0], xp0.y, wd0); ffma2(acc2[1][1], xp0.y, wd1);
                ffma2(acc2[1][2], xp0.y, wd2); ffma2(acc2[1][3], xp0.y, wd3);
                ffma2(acc2[2][0], xp1.x, wd0); ffma2(acc2[2][1], xp1.x, wd1);
                ffma2(acc2[2][2], xp1.x, wd2); ffma2(acc2[2][3], xp1.x, wd3);
                ffma2(acc2[3][0], xp1.y, wd0); ffma2(acc2[3][1], xp1.y, wd1);
                ffma2(acc2[3][2], xp1.y, wd2); ffma2(acc2[3][3], xp1.y, wd3);
            }
            if (blk + 1 < 4) {
                float4* dst = (float4*)(wbuf + (cur^1)*(KB*WD));
                #pragma unroll
                for (int i = 0; i < 4; ++i) dst[i*NTHR + tid] = nxt[i];
            }
            __syncthreads();
        }

        const int o = tx << 2;
        const float bo0 = bhsm[o], bo1 = bhsm[o+1], bo2 = bhsm[o+2], bo3 = bhsm[o+3];
        #pragma unroll
        for (int mp = 0; mp < 4; ++mp) {
            float e0, e1;
            unpack2(acc2[mp][0], e0, e1);
            oacc[2*mp][0]   += __sinf(5.f*(e0+bo0));
            oacc[2*mp+1][0] += __sinf(5.f*(e1+bo0));
            unpack2(acc2[mp][1], e0, e1);
            oacc[2*mp][1]   += __sinf(5.f*(e0+bo1));
            oacc[2*mp+1][1] += __sinf(5.f*(e1+bo1));
            unpack2(acc2[mp][2], e0, e1);
            oacc[2*mp][2]   += __sinf(5.f*(e0+bo2));
            oacc[2*mp+1][2] += __sinf(5.f*(e1+bo2));
            unpack2(acc2[mp][3], e0, e1);
            oacc[2*mp][3]   += __sinf(5.f*(e0+bo3));
            oacc[2*mp+1][3] += __sinf(5.f*(e1+bo3));
        }
    }

    /* ---- write output tile ---- */
    #pragma unroll
    for (int mi = 0; mi < 8; ++mi) {
        long row = base + m0 + mi;
        *(float4*)(outp + row*(long)OD + (tx<<2)) =
            make_float4(oacc[mi][0], oacc[mi][1], oacc[mi][2], oacc[mi][3]);
    }
}

extern "C" void kernel_launch(void* const* d_in, const int* in_sizes, int n_in,
                              void* d_out, int out_size) {
    /* map inputs by element count (all sizes are distinct) */
    const float *pos=0,*gfp=0,*ffn=0,*w0=0,*b0=0,*wh=0,*bh=0,*whh=0,*bhh=0;
    for (int i = 0; i < n_in; ++i) {
        const float* p = (const float*)d_in[i];
        switch (in_sizes[i]) {
            case NPTS*3:        pos = p; break;   /* in_pos     */
            case NPTS*GL*FD:    gfp = p; break;   /* grid_feats */
            case GL*FD*WD:      ffn = p; break;   /* ffn_A      */
            case 3*WD:          w0  = p; break;   /* W0         */
            case WD:            b0  = p; break;   /* b0         */
            case GL*WD*WD:      wh  = p; break;   /* Wh         */
            case GL*WD:         bh  = p; break;   /* bh         */
            case GL*WD*OD:      whh = p; break;   /* Wh_high    */
            case GL*OD:         bhh = p; break;   /* bh_high    */
        }
    }
    cudaFuncSetAttribute(ffb_kernel, cudaFuncAttributeMaxDynamicSharedMemorySize, SMEM_BYTES);
    ffb_kernel<<<NPTS/MTILE, NTHR, SMEM_BYTES>>>(pos, gfp, ffn, w0, b0,
                                                 wh, bh, whh, bhh, (float*)d_out);
}

// round 9
// speedup vs baseline: 1.5060x; 1.4279x over previous
#include <cuda_runtime.h>
#include <cuda_bf16.h>
#include <cstdint>

#define NPTS 131072
#define GL 5
#define WD 256
#define OD 64
#define MTILE 128
#define NTHR 256
#define CHUNKB 36864       /* uniform padded chunk: 256 thr x 144B */
#define NCHUNK_T 50        /* 10/layer: 4 Wm, 4 Wh, 1 Hm, 1 Hh */

#define XSTR 528           /* x row stride bytes (512 data + 16 pad) */
#define WSTR 528           /* main W row stride */
#define HSTR 144           /* head W row stride (128 data + 16 pad) */

/* pre-split weights, padded-stride layout: [0]=mid residual, [1]=hi */
__device__ __align__(1024) unsigned char g_wm[2][GL][4][CHUNKB];
__device__ __align__(1024) unsigned char g_wh[2][GL][CHUNKB];

/* ---- shared memory byte offsets ---- */
#define SM_XHI 0                 /* 128 rows x 528B */
#define SM_XLO 67584
#define SM_WR  135168            /* ring: 2 x 36864 */
#define SM_FFN 208896            /* 8 x 256 f32 */
#define SM_BH  217088            /* 5*bh: 256 f32 */
#define SM_BHH 218112            /* 5*bhh: 64 f32 */
#define SM_W0  218368            /* 3 x 256 f32 */
#define SM_B0  221440            /* 256 f32 */
#define SMEM_BYTES 222464

__device__ __forceinline__ uint32_t smem_u32(const void* p) {
    uint32_t a;
    asm("{ .reg .u64 t; cvta.to.shared.u64 t, %1; cvt.u32.u64 %0, t; }" : "=r"(a) : "l"(p));
    return a;
}

__device__ __forceinline__ void ldA(uint32_t* a, uint32_t addr) {
    asm volatile("ldmatrix.sync.aligned.m8n8.x4.shared.b16 {%0,%1,%2,%3}, [%4];"
        : "=r"(a[0]),"=r"(a[1]),"=r"(a[2]),"=r"(a[3]) : "r"(addr));
}
__device__ __forceinline__ void ldBt(uint32_t* b, uint32_t addr) {
    asm volatile("ldmatrix.sync.aligned.m8n8.x2.trans.shared.b16 {%0,%1}, [%2];"
        : "=r"(b[0]),"=r"(b[1]) : "r"(addr));
}
__device__ __forceinline__ void mma_bf16(float* c, const uint32_t* a, const uint32_t* b) {
    asm volatile("mma.sync.aligned.m16n8k16.row.col.f32.bf16.bf16.f32 "
        "{%0,%1,%2,%3},{%4,%5,%6,%7},{%8,%9},{%0,%1,%2,%3};"
        : "+f"(c[0]),"+f"(c[1]),"+f"(c[2]),"+f"(c[3])
        : "r"(a[0]),"r"(a[1]),"r"(a[2]),"r"(a[3]), "r"(b[0]),"r"(b[1]));
}

/* (v0,v1) -> bf16x2 hi word + bf16x2 residual word (UNSCALED — bf16 range covers) */
__device__ __forceinline__ void split2(float v0, float v1, uint32_t& hp, uint32_t& mp) {
    asm("cvt.rn.bf16x2.f32 %0, %1, %2;" : "=r"(hp) : "f"(v1), "f"(v0));
    float h0 = __uint_as_float(hp << 16);
    float h1 = __uint_as_float(hp & 0xffff0000u);
    asm("cvt.rn.bf16x2.f32 %0, %1, %2;" : "=r"(mp) : "f"(v1 - h1), "f"(v0 - h0));
}

__device__ __forceinline__ const unsigned char* chunk_ptr(int c) {
    int l = c / 10, j = c - l * 10;
    if (j < 4) return g_wm[0][l][j];        /* Wm */
    if (j < 8) return g_wm[1][l][j - 4];    /* Wh */
    return g_wh[j - 8][l];                  /* Hm, Hh */
}

__device__ __forceinline__ void issue_chunk(int c, uint32_t smb, int tid) {
    const unsigned char* src = chunk_ptr(c) + tid * 144;
    uint32_t dst = smb + SM_WR + (uint32_t)(c & 1) * CHUNKB + (uint32_t)tid * 144;
#pragma unroll
    for (int i = 0; i < 9; ++i)
        asm volatile("cp.async.cg.shared.global [%0], [%1], 16;"
            :: "r"(dst + i*16), "l"(src + i*16) : "memory");
    asm volatile("cp.async.commit_group;" ::: "memory");
}

/* ---------- prep: bf16 2-term split into padded-stride layout ---------- */
__global__ void prep_kernel(const float* __restrict__ wh, const float* __restrict__ whh) {
    int idx = blockIdx.x * blockDim.x + threadIdx.x;
    if (idx < GL*WD*WD) {
        int l = idx >> 16, r = idx & 65535, k = r >> 8, n = r & 255;
        float wv = wh[idx];
        __nv_bfloat16 h = __float2bfloat16(wv);
        __nv_bfloat16 m = __float2bfloat16(wv - __bfloat162float(h));
        int kc = k >> 6, kk = k & 63;
        uint32_t off = (uint32_t)kk*WSTR + (uint32_t)n*2;
        *(__nv_bfloat16*)&g_wm[1][l][kc][off] = h;
        *(__nv_bfloat16*)&g_wm[0][l][kc][off] = m;
    } else {
        int j = idx - GL*WD*WD;
        if (j < GL*WD*OD) {
            int l = j / (WD*OD), r = j % (WD*OD), k = r >> 6, o = r & 63;
            float wv = whh[j];
            __nv_bfloat16 h = __float2bfloat16(wv);
            __nv_bfloat16 m = __float2bfloat16(wv - __bfloat162float(h));
            uint32_t off = (uint32_t)k*HSTR + (uint32_t)o*2;
            *(__nv_bfloat16*)&g_wh[1][l][off] = h;
            *(__nv_bfloat16*)&g_wh[0][l][off] = m;
        }
    }
}

/* ---------- main fused kernel ---------- */
__global__ void __launch_bounds__(NTHR, 1)
ffb_mma(const float* __restrict__ pos, const float* __restrict__ gf,
        const float* __restrict__ ffnA, const float* __restrict__ w0g,
        const float* __restrict__ b0g, const float* __restrict__ bhv,
        const float* __restrict__ bhhg, float* __restrict__ outp)
{
    extern __shared__ __align__(1024) unsigned char sm[];
    float* ffnS = (float*)(sm + SM_FFN);
    float* bhs  = (float*)(sm + SM_BH);
    float* bhhs = (float*)(sm + SM_BHH);
    float* w0s  = (float*)(sm + SM_W0);
    float* b0s  = (float*)(sm + SM_B0);
    const uint32_t smb = smem_u32(sm);

    const int tid = threadIdx.x, w = tid >> 5, lane = tid & 31;
    const int wm = w & 3, wn = w >> 2;       /* warp grid 4m x 2n */
    const int g = lane >> 2, qi = lane & 3;
    const long base = (long)blockIdx.x * MTILE;

    /* ldmatrix lane geometry */
    const int atj = lane >> 3;
    const int a_row = (atj & 1)*8 + (lane & 7);
    const int a_cc  = atj >> 1;
    const int b_row = lane & 15;

    const int arow0 = 32*wm + a_row;
    const int arow1 = arow0 + 16;
    const uint32_t rbA0 = smb + (uint32_t)arow0*XSTR + (uint32_t)a_cc*16;
    const uint32_t rbA1 = smb + (uint32_t)arow1*XSTR + (uint32_t)a_cc*16;

    for (int i = tid; i < 768; i += NTHR) w0s[i] = w0g[i];
    for (int i = tid; i < 256; i += NTHR) b0s[i] = b0g[i];
    issue_chunk(0, smb, tid);
    issue_chunk(1, smb, tid);

    /* ---- layer 0: x = sin(5*(pos @ W0 + b0)) -> SMEM bf16 hi/mid ---- */
    {
        int r = tid >> 1, hh = tid & 1;
        float p0 = pos[(base + r)*3], p1 = pos[(base + r)*3 + 1], p2 = pos[(base + r)*3 + 2];
        const uint32_t rb = (uint32_t)r*XSTR;
#pragma unroll
        for (int c = 0; c < 128; c += 2) {
            int c0 = hh*128 + c;
            float h0 = fmaf(p0, w0s[c0],   fmaf(p1, w0s[256+c0],   fmaf(p2, w0s[512+c0],   b0s[c0])));
            float h1 = fmaf(p0, w0s[c0+1], fmaf(p1, w0s[256+c0+1], fmaf(p2, w0s[512+c0+1], b0s[c0+1])));
            float v0 = __sinf(5.0f*h0), v1 = __sinf(5.0f*h1);
            uint32_t hp, mp; split2(v0, v1, hp, mp);
            uint32_t off = rb + (uint32_t)c0*2;
            *(uint32_t*)(sm + SM_XHI + off) = hp;
            *(uint32_t*)(sm + SM_XLO + off) = mp;
        }
    }

    float oacc[2][4][4];
#pragma unroll
    for (int a = 0; a < 2; ++a)
#pragma unroll
        for (int b = 0; b < 4; ++b)
#pragma unroll
            for (int q = 0; q < 4; ++q) oacc[a][b][q] = 0.f;

    int cc = 0;

    for (int l = 0; l < GL; ++l) {
        __syncthreads();
        {
            float gsc = 6.283185307179586f * (float)(1 << l);
            for (int i = tid; i < 2048; i += NTHR) ffnS[i] = ffnA[l*2048 + i] * gsc;
            for (int i = tid; i < 256;  i += NTHR) bhs[i]  = 5.0f * bhv[l*256 + i];
            for (int i = tid; i < 64;   i += NTHR) bhhs[i] = 5.0f * bhhg[l*64 + i];
        }

        float acc[2][16][4];
#pragma unroll
        for (int mt = 0; mt < 2; ++mt)
#pragma unroll
            for (int nt = 0; nt < 16; ++nt)
#pragma unroll
                for (int q = 0; q < 4; ++q) acc[mt][nt][q] = 0.f;

        /* ---- main GEMM: pass0 = Wm x (Ah+Am), pass1 = Wh x (Ah+Am); NO scaling ---- */
#pragma unroll
        for (int pass = 0; pass < 2; ++pass) {
            for (int kc = 0; kc < 4; ++kc) {
                if (cc + 1 < NCHUNK_T) asm volatile("cp.async.wait_group 1;" ::: "memory");
                else                   asm volatile("cp.async.wait_group 0;" ::: "memory");
                __syncthreads();
                const uint32_t slot = smb + SM_WR + (uint32_t)(cc & 1)*CHUNKB;
                for (int ks = 0; ks < 4; ++ks) {
                    const int k = kc*64 + ks*16;
                    const uint32_t koff = (uint32_t)(k >> 3) * 16;
                    uint32_t ah0[4], ah1[4], am0[4], am1[4];
                    ldA(ah0, rbA0 + SM_XHI + koff);
                    ldA(ah1, rbA1 + SM_XHI + koff);
                    ldA(am0, rbA0 + SM_XLO + koff);
                    ldA(am1, rbA1 + SM_XLO + koff);
                    const uint32_t brow = slot + (uint32_t)(ks*16 + b_row)*WSTR + (uint32_t)(wn*16)*16;
#pragma unroll
                    for (int nt = 0; nt < 16; ++nt) {
                        uint32_t b[2];
                        ldBt(b, brow + (uint32_t)nt*16);
                        mma_bf16(acc[0][nt], ah0, b);
                        mma_bf16(acc[1][nt], ah1, b);
                        mma_bf16(acc[0][nt], am0, b);
                        mma_bf16(acc[1][nt], am1, b);
                    }
                }
                __syncthreads();
                if (cc + 2 < NCHUNK_T) issue_chunk(cc + 2, smb, tid);
                ++cc;
            }
        }

        /* ---- epilogue: x_new = sin(5*D + 5*bh) + sin(gf @ ffnS) ---- */
#pragma unroll
        for (int mt = 0; mt < 2; ++mt) {
            const int r0 = 32*wm + 16*mt + g;
            float gfa[2][8];
#pragma unroll
            for (int p = 0; p < 2; ++p) {
                const float* gp = gf + (base + r0 + 8*p)*40 + l*8;
                float4 u = *(const float4*)gp, v2 = *(const float4*)(gp + 4);
                gfa[p][0]=u.x; gfa[p][1]=u.y; gfa[p][2]=u.z; gfa[p][3]=u.w;
                gfa[p][4]=v2.x; gfa[p][5]=v2.y; gfa[p][6]=v2.z; gfa[p][7]=v2.w;
            }
#pragma unroll
            for (int nt = 0; nt < 16; ++nt) {
                const int n0 = 128*wn + 8*nt + 2*qi;
                float rs00=0.f, rs01=0.f, rs10=0.f, rs11=0.f;
#pragma unroll
                for (int f = 0; f < 8; ++f) {
                    float2 fp = *(const float2*)&ffnS[f*256 + n0];
                    rs00 = fmaf(gfa[0][f], fp.x, rs00);
                    rs01 = fmaf(gfa[0][f], fp.y, rs01);
                    rs10 = fmaf(gfa[1][f], fp.x, rs10);
                    rs11 = fmaf(gfa[1][f], fp.y, rs11);
                }
                const float bh0 = bhs[n0], bh1 = bhs[n0+1];
                float v00 = __sinf(fmaf(acc[mt][nt][0], 5.0f, bh0)) + __sinf(rs00);
                float v01 = __sinf(fmaf(acc[mt][nt][1], 5.0f, bh1)) + __sinf(rs01);
                float v10 = __sinf(fmaf(acc[mt][nt][2], 5.0f, bh0)) + __sinf(rs10);
                float v11 = __sinf(fmaf(acc[mt][nt][3], 5.0f, bh1)) + __sinf(rs11);
                uint32_t hp, mp;
                split2(v00, v01, hp, mp);
                uint32_t off = (uint32_t)r0*XSTR + (uint32_t)n0*2;
                *(uint32_t*)(sm + SM_XHI + off) = hp;
                *(uint32_t*)(sm + SM_XLO + off) = mp;
                split2(v10, v11, hp, mp);
                off = (uint32_t)(r0+8)*XSTR + (uint32_t)n0*2;
                *(uint32_t*)(sm + SM_XHI + off) = hp;
                *(uint32_t*)(sm + SM_XLO + off) = mp;
            }
        }

        /* ---- head GEMM: pass0 = Hm chunk, pass1 = Hh chunk; NO scaling ---- */
        float acc2[2][4][4];
#pragma unroll
        for (int mt = 0; mt < 2; ++mt)
#pragma unroll
            for (int nt = 0; nt < 4; ++nt)
#pragma unroll
                for (int q = 0; q < 4; ++q) acc2[mt][nt][q] = 0.f;

#pragma unroll
        for (int pass = 0; pass < 2; ++pass) {
            if (cc + 1 < NCHUNK_T) asm volatile("cp.async.wait_group 1;" ::: "memory");
            else                   asm volatile("cp.async.wait_group 0;" ::: "memory");
            __syncthreads();
            const uint32_t slot = smb + SM_WR + (uint32_t)(cc & 1)*CHUNKB;
            for (int ks = 0; ks < 16; ++ks) {
                const int k = ks*16;
                const uint32_t koff = (uint32_t)(k >> 3) * 16;
                uint32_t ah0[4], ah1[4], am0[4], am1[4];
                ldA(ah0, rbA0 + SM_XHI + koff);
                ldA(ah1, rbA1 + SM_XHI + koff);
                ldA(am0, rbA0 + SM_XLO + koff);
                ldA(am1, rbA1 + SM_XLO + koff);
                const uint32_t brow = slot + (uint32_t)(k + b_row)*HSTR + (uint32_t)(wn*4)*16;
#pragma unroll
                for (int nt = 0; nt < 4; ++nt) {
                    uint32_t b[2];
                    ldBt(b, brow + (uint32_t)nt*16);
                    mma_bf16(acc2[0][nt], ah0, b);
                    mma_bf16(acc2[1][nt], ah1, b);
                    mma_bf16(acc2[0][nt], am0, b);
                    mma_bf16(acc2[1][nt], am1, b);
                }
            }
            __syncthreads();
            if (cc + 2 < NCHUNK_T) issue_chunk(cc + 2, smb, tid);
            ++cc;
        }

        /* ---- head epilogue: out += sin(5*D2 + 5*bhh) ---- */
#pragma unroll
        for (int mt = 0; mt < 2; ++mt)
#pragma unroll
            for (int nt = 0; nt < 4; ++nt) {
                const int n0 = 32*wn + 8*nt + 2*qi;
                const float bh0 = bhhs[n0], bh1 = bhhs[n0+1];
                oacc[mt][nt][0] += __sinf(fmaf(acc2[mt][nt][0], 5.0f, bh0));
                oacc[mt][nt][1] += __sinf(fmaf(acc2[mt][nt][1], 5.0f, bh1));
                oacc[mt][nt][2] += __sinf(fmaf(acc2[mt][nt][2], 5.0f, bh0));
                oacc[mt][nt][3] += __sinf(fmaf(acc2[mt][nt][3], 5.0f, bh1));
            }
    }

    /* ---- output ---- */
#pragma unroll
    for (int mt = 0; mt < 2; ++mt)
#pragma unroll
        for (int p = 0; p < 2; ++p) {
            const long row = base + 32*wm + 16*mt + g + 8*p;
#pragma unroll
            for (int nt = 0; nt < 4; ++nt) {
                const int n0 = 32*wn + 8*nt + 2*qi;
                float2 v;
                v.x = oacc[mt][nt][2*p];
                v.y = oacc[mt][nt][2*p + 1];
                *(float2*)(outp + row*(long)OD + n0) = v;
            }
        }
}

extern "C" void kernel_launch(void* const* d_in, const int* in_sizes, int n_in,
                              void* d_out, int out_size) {
    const float *pos=0,*gfp=0,*ffn=0,*w0=0,*b0=0,*wh=0,*bh=0,*whh=0,*bhh=0;
    for (int i = 0; i < n_in; ++i) {
        const float* p = (const float*)d_in[i];
        switch (in_sizes[i]) {
            case NPTS*3:      pos = p; break;
            case NPTS*GL*8:   gfp = p; break;
            case GL*8*WD:     ffn = p; break;
            case 3*WD:        w0  = p; break;
            case WD:          b0  = p; break;
            case GL*WD*WD:    wh  = p; break;
            case GL*WD:       bh  = p; break;
            case GL*WD*OD:    whh = p; break;
            case GL*OD:       bhh = p; break;
        }
    }
    prep_kernel<<<(GL*WD*WD + GL*WD*OD)/256, 256>>>(wh, whh);
    cudaFuncSetAttribute(ffb_mma, cudaFuncAttributeMaxDynamicSharedMemorySize, SMEM_BYTES);
    ffb_mma<<<NPTS/MTILE, NTHR, SMEM_BYTES>>>(pos, gfp, ffn, w0, b0, bh, bhh, (float*)d_out);
}

// round 11
// speedup vs baseline: 1.5982x; 1.0612x over previous
#include <cuda_runtime.h>
#include <cuda_bf16.h>
#include <cstdint>

#define NPTS 131072
#define GL 5
#define WD 256
#define OD 64
#define MTILE 128
#define NTHR 512
#define CHUNKB 36864       /* uniform padded chunk */
#define NCHUNK_T 50        /* 10/layer: 4 Wm, 4 Wh, 1 Hm, 1 Hh */

#define XSTR 528           /* x row stride bytes (512 data + 16 pad) */
#define WSTR 528           /* main W row stride */
#define HSTR 144           /* head W row stride (128 data + 16 pad) */

/* pre-split weights, padded-stride layout: [0]=mid residual, [1]=hi */
__device__ __align__(1024) unsigned char g_wm[2][GL][4][CHUNKB];
__device__ __align__(1024) unsigned char g_wh[2][GL][CHUNKB];

/* ---- shared memory byte offsets ---- */
#define SM_XHI 0                 /* 128 rows x 528B */
#define SM_XLO 67584
#define SM_WR  135168            /* ring: 2 x 36864 */
#define SM_FFN 208896            /* 8 x 256 f32 */
#define SM_BH  217088            /* 5*bh: 256 f32 */
#define SM_BHH 218112            /* 5*bhh: 64 f32 */
#define SM_W0  218368            /* 3 x 256 f32 */
#define SM_B0  221440            /* 256 f32 */
#define SMEM_BYTES 222464

__device__ __forceinline__ uint32_t smem_u32(const void* p) {
    uint32_t a;
    asm("{ .reg .u64 t; cvta.to.shared.u64 t, %1; cvt.u32.u64 %0, t; }" : "=r"(a) : "l"(p));
    return a;
}

__device__ __forceinline__ void ldA(uint32_t* a, uint32_t addr) {
    asm volatile("ldmatrix.sync.aligned.m8n8.x4.shared.b16 {%0,%1,%2,%3}, [%4];"
        : "=r"(a[0]),"=r"(a[1]),"=r"(a[2]),"=r"(a[3]) : "r"(addr));
}
__device__ __forceinline__ void ldBt(uint32_t* b, uint32_t addr) {
    asm volatile("ldmatrix.sync.aligned.m8n8.x2.trans.shared.b16 {%0,%1}, [%2];"
        : "=r"(b[0]),"=r"(b[1]) : "r"(addr));
}
__device__ __forceinline__ void mma_bf16(float* c, const uint32_t* a, const uint32_t* b) {
    asm volatile("mma.sync.aligned.m16n8k16.row.col.f32.bf16.bf16.f32 "
        "{%0,%1,%2,%3},{%4,%5,%6,%7},{%8,%9},{%0,%1,%2,%3};"
        : "+f"(c[0]),"+f"(c[1]),"+f"(c[2]),"+f"(c[3])
        : "r"(a[0]),"r"(a[1]),"r"(a[2]),"r"(a[3]), "r"(b[0]),"r"(b[1]));
}

/* (v0,v1) -> bf16x2 hi word + bf16x2 residual word (unscaled) */
__device__ __forceinline__ void split2(float v0, float v1, uint32_t& hp, uint32_t& mp) {
    asm("cvt.rn.bf16x2.f32 %0, %1, %2;" : "=r"(hp) : "f"(v1), "f"(v0));
    float h0 = __uint_as_float(hp << 16);
    float h1 = __uint_as_float(hp & 0xffff0000u);
    asm("cvt.rn.bf16x2.f32 %0, %1, %2;" : "=r"(mp) : "f"(v1 - h1), "f"(v0 - h0));
}

__device__ __forceinline__ const unsigned char* chunk_ptr(int c) {
    int l = c / 10, j = c - l * 10;
    if (j < 4) return g_wm[0][l][j];        /* Wm */
    if (j < 8) return g_wm[1][l][j - 4];    /* Wh */
    return g_wh[j - 8][l];                  /* Hm, Hh */
}

__device__ __forceinline__ void issue_chunk(int c, uint32_t smb, int tid) {
    if (tid < 288) {   /* 288 threads x 128B = 36864 */
        const unsigned char* src = chunk_ptr(c) + tid * 128;
        uint32_t dst = smb + SM_WR + (uint32_t)(c & 1) * CHUNKB + (uint32_t)tid * 128;
#pragma unroll
        for (int i = 0; i < 8; ++i)
            asm volatile("cp.async.cg.shared.global [%0], [%1], 16;"
                :: "r"(dst + i*16), "l"(src + i*16) : "memory");
    }
    asm volatile("cp.async.commit_group;" ::: "memory");
}

/* ---------- prep: bf16 2-term split into padded-stride layout ---------- */
__global__ void prep_kernel(const float* __restrict__ wh, const float* __restrict__ whh) {
    int idx = blockIdx.x * blockDim.x + threadIdx.x;
    if (idx < GL*WD*WD) {
        int l = idx >> 16, r = idx & 65535, k = r >> 8, n = r & 255;
        float wv = wh[idx];
        __nv_bfloat16 h = __float2bfloat16(wv);
        __nv_bfloat16 m = __float2bfloat16(wv - __bfloat162float(h));
        int kc = k >> 6, kk = k & 63;
        uint32_t off = (uint32_t)kk*WSTR + (uint32_t)n*2;
        *(__nv_bfloat16*)&g_wm[1][l][kc][off] = h;
        *(__nv_bfloat16*)&g_wm[0][l][kc][off] = m;
    } else {
        int j = idx - GL*WD*WD;
        if (j < GL*WD*OD) {
            int l = j / (WD*OD), r = j % (WD*OD), k = r >> 6, o = r & 63;
            float wv = whh[j];
            __nv_bfloat16 h = __float2bfloat16(wv);
            __nv_bfloat16 m = __float2bfloat16(wv - __bfloat162float(h));
            uint32_t off = (uint32_t)k*HSTR + (uint32_t)o*2;
            *(__nv_bfloat16*)&g_wh[1][l][off] = h;
            *(__nv_bfloat16*)&g_wh[0][l][off] = m;
        }
    }
}

/* ---------- main fused kernel: 512 thr, warp grid 4m x 4n, 3-term split ---------- */
__global__ void __launch_bounds__(NTHR, 1)
ffb_mma(const float* __restrict__ pos, const float* __restrict__ gf,
        const float* __restrict__ ffnA, const float* __restrict__ w0g,
        const float* __restrict__ b0g, const float* __restrict__ bhv,
        const float* __restrict__ bhhg, float* __restrict__ outp)
{
    extern __shared__ __align__(1024) unsigned char sm[];
    float* ffnS = (float*)(sm + SM_FFN);
    float* bhs  = (float*)(sm + SM_BH);
    float* bhhs = (float*)(sm + SM_BHH);
    float* w0s  = (float*)(sm + SM_W0);
    float* b0s  = (float*)(sm + SM_B0);
    const uint32_t smb = smem_u32(sm);

    const int tid = threadIdx.x, w = tid >> 5, lane = tid & 31;
    const int wm = w & 3, wn = w >> 2;       /* warp grid 4m x 4n */
    const int g = lane >> 2, qi = lane & 3;
    const long base = (long)blockIdx.x * MTILE;

    /* ldmatrix lane geometry */
    const int atj = lane >> 3;
    const int a_row = (atj & 1)*8 + (lane & 7);
    const int a_cc  = atj >> 1;
    const int b_row = lane & 15;

    const int arow0 = 32*wm + a_row;
    const int arow1 = arow0 + 16;
    const uint32_t rbA0 = smb + (uint32_t)arow0*XSTR + (uint32_t)a_cc*16;
    const uint32_t rbA1 = smb + (uint32_t)arow1*XSTR + (uint32_t)a_cc*16;

    for (int i = tid; i < 768; i += NTHR) w0s[i] = w0g[i];
    for (int i = tid; i < 256; i += NTHR) b0s[i] = b0g[i];
    issue_chunk(0, smb, tid);
    issue_chunk(1, smb, tid);
    __syncthreads();   /* w0s/b0s staging must complete before layer-0 reads (R10 race fix) */

    /* ---- layer 0: x = sin(5*(pos @ W0 + b0)) -> SMEM bf16 hi/mid ---- */
    {
        int r = tid >> 2, q = tid & 3;       /* 512 thr: 128 rows x 4 col-quarters */
        float p0 = pos[(base + r)*3], p1 = pos[(base + r)*3 + 1], p2 = pos[(base + r)*3 + 2];
        const uint32_t rb = (uint32_t)r*XSTR;
#pragma unroll
        for (int c = 0; c < 64; c += 2) {
            int c0 = q*64 + c;
            float h0 = fmaf(p0, w0s[c0],   fmaf(p1, w0s[256+c0],   fmaf(p2, w0s[512+c0],   b0s[c0])));
            float h1 = fmaf(p0, w0s[c0+1], fmaf(p1, w0s[256+c0+1], fmaf(p2, w0s[512+c0+1], b0s[c0+1])));
            float v0 = __sinf(5.0f*h0), v1 = __sinf(5.0f*h1);
            uint32_t hp, mp; split2(v0, v1, hp, mp);
            uint32_t off = rb + (uint32_t)c0*2;
            *(uint32_t*)(sm + SM_XHI + off) = hp;
            *(uint32_t*)(sm + SM_XLO + off) = mp;
        }
    }

    float oacc[2][2][4];
#pragma unroll
    for (int a = 0; a < 2; ++a)
#pragma unroll
        for (int b = 0; b < 2; ++b)
#pragma unroll
            for (int q = 0; q < 4; ++q) oacc[a][b][q] = 0.f;

    int cc = 0;

    for (int l = 0; l < GL; ++l) {
        __syncthreads();
        {
            float gsc = 6.283185307179586f * (float)(1 << l);
            for (int i = tid; i < 2048; i += NTHR) ffnS[i] = ffnA[l*2048 + i] * gsc;
            for (int i = tid; i < 256;  i += NTHR) bhs[i]  = 5.0f * bhv[l*256 + i];
            for (int i = tid; i < 64;   i += NTHR) bhhs[i] = 5.0f * bhhg[l*64 + i];
        }

        float acc[2][8][4];
#pragma unroll
        for (int mt = 0; mt < 2; ++mt)
#pragma unroll
            for (int nt = 0; nt < 8; ++nt)
#pragma unroll
                for (int q = 0; q < 4; ++q) acc[mt][nt][q] = 0.f;

        /* ---- main GEMM (3-term): pass0 = Wm x Ah; pass1 = Wh x (Ah+Am) ---- */
#pragma unroll
        for (int pass = 0; pass < 2; ++pass) {
            for (int kc = 0; kc < 4; ++kc) {
                if (cc + 1 < NCHUNK_T) asm volatile("cp.async.wait_group 1;" ::: "memory");
                else                   asm volatile("cp.async.wait_group 0;" ::: "memory");
                __syncthreads();
                const uint32_t slot = smb + SM_WR + (uint32_t)(cc & 1)*CHUNKB;
                for (int ks = 0; ks < 4; ++ks) {
                    const int k = kc*64 + ks*16;
                    const uint32_t koff = (uint32_t)(k >> 3) * 16;
                    uint32_t ah0[4], ah1[4], am0[4], am1[4];
                    ldA(ah0, rbA0 + SM_XHI + koff);
                    ldA(ah1, rbA1 + SM_XHI + koff);
                    if (pass == 1) {
                        ldA(am0, rbA0 + SM_XLO + koff);
                        ldA(am1, rbA1 + SM_XLO + koff);
                    }
                    const uint32_t brow = slot + (uint32_t)(ks*16 + b_row)*WSTR + (uint32_t)(wn*8)*16;
#pragma unroll
                    for (int nt = 0; nt < 8; ++nt) {
                        uint32_t b[2];
                        ldBt(b, brow + (uint32_t)nt*16);
                        mma_bf16(acc[0][nt], ah0, b);
                        mma_bf16(acc[1][nt], ah1, b);
                        if (pass == 1) {
                            mma_bf16(acc[0][nt], am0, b);
                            mma_bf16(acc[1][nt], am1, b);
                        }
                    }
                }
                __syncthreads();
                if (cc + 2 < NCHUNK_T) issue_chunk(cc + 2, smb, tid);
                ++cc;
            }
        }

        /* ---- epilogue: x_new = sin(5*D + 5*bh) + sin(gf @ ffnS) ---- */
#pragma unroll
        for (int mt = 0; mt < 2; ++mt) {
            const int r0 = 32*wm + 16*mt + g;
            float gfa[2][8];
#pragma unroll
            for (int p = 0; p < 2; ++p) {
                const float* gp = gf + (base + r0 + 8*p)*40 + l*8;
                float4 u = *(const float4*)gp, v2 = *(const float4*)(gp + 4);
                gfa[p][0]=u.x; gfa[p][1]=u.y; gfa[p][2]=u.z; gfa[p][3]=u.w;
                gfa[p][4]=v2.x; gfa[p][5]=v2.y; gfa[p][6]=v2.z; gfa[p][7]=v2.w;
            }
#pragma unroll
            for (int nt = 0; nt < 8; ++nt) {
                const int n0 = 64*wn + 8*nt + 2*qi;
                float rs00=0.f, rs01=0.f, rs10=0.f, rs11=0.f;
#pragma unroll
                for (int f = 0; f < 8; ++f) {
                    float2 fp = *(const float2*)&ffnS[f*256 + n0];
                    rs00 = fmaf(gfa[0][f], fp.x, rs00);
                    rs01 = fmaf(gfa[0][f], fp.y, rs01);
                    rs10 = fmaf(gfa[1][f], fp.x, rs10);
                    rs11 = fmaf(gfa[1][f], fp.y, rs11);
                }
                const float bh0 = bhs[n0], bh1 = bhs[n0+1];
                float v00 = __sinf(fmaf(acc[mt][nt][0], 5.0f, bh0)) + __sinf(rs00);
                float v01 = __sinf(fmaf(acc[mt][nt][1], 5.0f, bh1)) + __sinf(rs01);
                float v10 = __sinf(fmaf(acc[mt][nt][2], 5.0f, bh0)) + __sinf(rs10);
                float v11 = __sinf(fmaf(acc[mt][nt][3], 5.0f, bh1)) + __sinf(rs11);
                uint32_t hp, mp;
                split2(v00, v01, hp, mp);
                uint32_t off = (uint32_t)r0*XSTR + (uint32_t)n0*2;
                *(uint32_t*)(sm + SM_XHI + off) = hp;
                *(uint32_t*)(sm + SM_XLO + off) = mp;
                split2(v10, v11, hp, mp);
                off = (uint32_t)(r0+8)*XSTR + (uint32_t)n0*2;
                *(uint32_t*)(sm + SM_XHI + off) = hp;
                *(uint32_t*)(sm + SM_XLO + off) = mp;
            }
        }

        /* ---- head GEMM (3-term): pass0 = Hm x Ah; pass1 = Hh x (Ah+Am) ---- */
        float acc2[2][2][4];
#pragma unroll
        for (int mt = 0; mt < 2; ++mt)
#pragma unroll
            for (int nt = 0; nt < 2; ++nt)
#pragma unroll
                for (int q = 0; q < 4; ++q) acc2[mt][nt][q] = 0.f;

#pragma unroll
        for (int pass = 0; pass < 2; ++pass) {
            if (cc + 1 < NCHUNK_T) asm volatile("cp.async.wait_group 1;" ::: "memory");
            else                   asm volatile("cp.async.wait_group 0;" ::: "memory");
            __syncthreads();
            const uint32_t slot = smb + SM_WR + (uint32_t)(cc & 1)*CHUNKB;
            for (int ks = 0; ks < 16; ++ks) {
                const int k = ks*16;
                const uint32_t koff = (uint32_t)(k >> 3) * 16;
                uint32_t ah0[4], ah1[4], am0[4], am1[4];
                ldA(ah0, rbA0 + SM_XHI + koff);
                ldA(ah1, rbA1 + SM_XHI + koff);
                if (pass == 1) {
                    ldA(am0, rbA0 + SM_XLO + koff);
                    ldA(am1, rbA1 + SM_XLO + koff);
                }
                const uint32_t brow = slot + (uint32_t)(k + b_row)*HSTR + (uint32_t)(wn*2)*16;
#pragma unroll
                for (int nt = 0; nt < 2; ++nt) {
                    uint32_t b[2];
                    ldBt(b, brow + (uint32_t)nt*16);
                    mma_bf16(acc2[0][nt], ah0, b);
                    mma_bf16(acc2[1][nt], ah1, b);
                    if (pass == 1) {
                        mma_bf16(acc2[0][nt], am0, b);
                        mma_bf16(acc2[1][nt], am1, b);
                    }
                }
            }
            __syncthreads();
            if (cc + 2 < NCHUNK_T) issue_chunk(cc + 2, smb, tid);
            ++cc;
        }

        /* ---- head epilogue: out += sin(5*D2 + 5*bhh) ---- */
#pragma unroll
        for (int mt = 0; mt < 2; ++mt)
#pragma unroll
            for (int nt = 0; nt < 2; ++nt) {
                const int n0 = 16*wn + 8*nt + 2*qi;
                const float bh0 = bhhs[n0], bh1 = bhhs[n0+1];
                oacc[mt][nt][0] += __sinf(fmaf(acc2[mt][nt][0], 5.0f, bh0));
                oacc[mt][nt][1] += __sinf(fmaf(acc2[mt][nt][1], 5.0f, bh1));
                oacc[mt][nt][2] += __sinf(fmaf(acc2[mt][nt][2], 5.0f, bh0));
                oacc[mt][nt][3] += __sinf(fmaf(acc2[mt][nt][3], 5.0f, bh1));
            }
    }

    /* ---- output ---- */
#pragma unroll
    for (int mt = 0; mt < 2; ++mt)
#pragma unroll
        for (int p = 0; p < 2; ++p) {
            const long row = base + 32*wm + 16*mt + g + 8*p;
#pragma unroll
            for (int nt = 0; nt < 2; ++nt) {
                const int n0 = 16*wn + 8*nt + 2*qi;
                float2 v;
                v.x = oacc[mt][nt][2*p];
                v.y = oacc[mt][nt][2*p + 1];
                *(float2*)(outp + row*(long)OD + n0) = v;
            }
        }
}

extern "C" void kernel_launch(void* const* d_in, const int* in_sizes, int n_in,
                              void* d_out, int out_size) {
    const float *pos=0,*gfp=0,*ffn=0,*w0=0,*b0=0,*wh=0,*bh=0,*whh=0,*bhh=0;
    for (int i = 0; i < n_in; ++i) {
        const float* p = (const float*)d_in[i];
        switch (in_sizes[i]) {
            case NPTS*3:      pos = p; break;
            case NPTS*GL*8:   gfp = p; break;
            case GL*8*WD:     ffn = p; break;
            case 3*WD:        w0  = p; break;
            case WD:          b0  = p; break;
            case GL*WD*WD:    wh  = p; break;
            case GL*WD:       bh  = p; break;
            case GL*WD*OD:    whh = p; break;
            case GL*OD:       bhh = p; break;
        }
    }
    prep_kernel<<<(GL*WD*WD + GL*WD*OD)/256, 256>>>(wh, whh);
    cudaFuncSetAttribute(ffb_mma, cudaFuncAttributeMaxDynamicSharedMemorySize, SMEM_BYTES);
    ffb_mma<<<NPTS/MTILE, NTHR, SMEM_BYTES>>>(pos, gfp, ffn, w0, b0, bh, bhh, (float*)d_out);
}

// round 12
// speedup vs baseline: 1.6201x; 1.0137x over previous
#include <cuda_runtime.h>
#include <cuda_bf16.h>
#include <cstdint>

#define NPTS 131072
#define GL 5
#define WD 256
#define OD 64
#define MTILE 128
#define NTHR 512
#define CHUNKB 36864       /* uniform padded chunk */
#define NCHUNK_T 50        /* 10/layer: 4 Wm, 4 Wh, 1 Hm, 1 Hh */

#define XSTR 528           /* x row stride bytes (512 data + 16 pad) */
#define WSTR 528           /* main W row stride */
#define HSTR 144           /* head W row stride (128 data + 16 pad) */

/* pre-split weights, padded-stride layout: [0]=mid residual, [1]=hi */
__device__ __align__(1024) unsigned char g_wm[2][GL][4][CHUNKB];
__device__ __align__(1024) unsigned char g_wh[2][GL][CHUNKB];

/* ---- shared memory byte offsets ---- */
#define SM_XHI 0                 /* 128 rows x 528B */
#define SM_XLO 67584
#define SM_WR  135168            /* ring: 2 x 36864 */
#define SM_FFN 208896            /* 8 x 256 f32 */
#define SM_BH  217088            /* 5*bh: 256 f32 */
#define SM_BHH 218112            /* 5*bhh: 64 f32 */
#define SM_W0  218368            /* 3 x 256 f32 */
#define SM_B0  221440            /* 256 f32 */
#define SMEM_BYTES 222464

__device__ __forceinline__ uint32_t smem_u32(const void* p) {
    uint32_t a;
    asm("{ .reg .u64 t; cvta.to.shared.u64 t, %1; cvt.u32.u64 %0, t; }" : "=r"(a) : "l"(p));
    return a;
}

__device__ __forceinline__ void ldA(uint32_t* a, uint32_t addr) {
    asm volatile("ldmatrix.sync.aligned.m8n8.x4.shared.b16 {%0,%1,%2,%3}, [%4];"
        : "=r"(a[0]),"=r"(a[1]),"=r"(a[2]),"=r"(a[3]) : "r"(addr));
}
/* x4 trans: mats 0/1 = rows k..k+15 @ col n0 (nt), mats 2/3 = same rows @ col n0+8 (nt+1) */
__device__ __forceinline__ void ldBt4(uint32_t* b, uint32_t addr) {
    asm volatile("ldmatrix.sync.aligned.m8n8.x4.trans.shared.b16 {%0,%1,%2,%3}, [%4];"
        : "=r"(b[0]),"=r"(b[1]),"=r"(b[2]),"=r"(b[3]) : "r"(addr));
}
__device__ __forceinline__ void mma_bf16(float* c, const uint32_t* a, const uint32_t* b) {
    asm volatile("mma.sync.aligned.m16n8k16.row.col.f32.bf16.bf16.f32 "
        "{%0,%1,%2,%3},{%4,%5,%6,%7},{%8,%9},{%0,%1,%2,%3};"
        : "+f"(c[0]),"+f"(c[1]),"+f"(c[2]),"+f"(c[3])
        : "r"(a[0]),"r"(a[1]),"r"(a[2]),"r"(a[3]), "r"(b[0]),"r"(b[1]));
}

/* (v0,v1) -> bf16x2 hi word + bf16x2 residual word (unscaled) */
__device__ __forceinline__ void split2(float v0, float v1, uint32_t& hp, uint32_t& mp) {
    asm("cvt.rn.bf16x2.f32 %0, %1, %2;" : "=r"(hp) : "f"(v1), "f"(v0));
    float h0 = __uint_as_float(hp << 16);
    float h1 = __uint_as_float(hp & 0xffff0000u);
    asm("cvt.rn.bf16x2.f32 %0, %1, %2;" : "=r"(mp) : "f"(v1 - h1), "f"(v0 - h0));
}

__device__ __forceinline__ const unsigned char* chunk_ptr(int c) {
    int l = c / 10, j = c - l * 10;
    if (j < 4) return g_wm[0][l][j];        /* Wm */
    if (j < 8) return g_wm[1][l][j - 4];    /* Wh */
    return g_wh[j - 8][l];                  /* Hm, Hh */
}

__device__ __forceinline__ void issue_chunk(int c, uint32_t smb, int tid) {
    if (tid < 288) {   /* 288 threads x 128B = 36864 */
        const unsigned char* src = chunk_ptr(c) + tid * 128;
        uint32_t dst = smb + SM_WR + (uint32_t)(c & 1) * CHUNKB + (uint32_t)tid * 128;
#pragma unroll
        for (int i = 0; i < 8; ++i)
            asm volatile("cp.async.cg.shared.global [%0], [%1], 16;"
                :: "r"(dst + i*16), "l"(src + i*16) : "memory");
    }
    asm volatile("cp.async.commit_group;" ::: "memory");
}

/* ---------- prep: bf16 2-term split into padded-stride layout ---------- */
__global__ void prep_kernel(const float* __restrict__ wh, const float* __restrict__ whh) {
    int idx = blockIdx.x * blockDim.x + threadIdx.x;
    if (idx < GL*WD*WD) {
        int l = idx >> 16, r = idx & 65535, k = r >> 8, n = r & 255;
        float wv = wh[idx];
        __nv_bfloat16 h = __float2bfloat16(wv);
        __nv_bfloat16 m = __float2bfloat16(wv - __bfloat162float(h));
        int kc = k >> 6, kk = k & 63;
        uint32_t off = (uint32_t)kk*WSTR + (uint32_t)n*2;
        *(__nv_bfloat16*)&g_wm[1][l][kc][off] = h;
        *(__nv_bfloat16*)&g_wm[0][l][kc][off] = m;
    } else {
        int j = idx - GL*WD*WD;
        if (j < GL*WD*OD) {
            int l = j / (WD*OD), r = j % (WD*OD), k = r >> 6, o = r & 63;
            float wv = whh[j];
            __nv_bfloat16 h = __float2bfloat16(wv);
            __nv_bfloat16 m = __float2bfloat16(wv - __bfloat162float(h));
            uint32_t off = (uint32_t)k*HSTR + (uint32_t)o*2;
            *(__nv_bfloat16*)&g_wh[1][l][off] = h;
            *(__nv_bfloat16*)&g_wh[0][l][off] = m;
        }
    }
}

/* ---------- main fused kernel: 512 thr, warp grid 4m x 4n, 3-term split ---------- */
__global__ void __launch_bounds__(NTHR, 1)
ffb_mma(const float* __restrict__ pos, const float* __restrict__ gf,
        const float* __restrict__ ffnA, const float* __restrict__ w0g,
        const float* __restrict__ b0g, const float* __restrict__ bhv,
        const float* __restrict__ bhhg, float* __restrict__ outp)
{
    extern __shared__ __align__(1024) unsigned char sm[];
    float* ffnS = (float*)(sm + SM_FFN);
    float* bhs  = (float*)(sm + SM_BH);
    float* bhhs = (float*)(sm + SM_BHH);
    float* w0s  = (float*)(sm + SM_W0);
    float* b0s  = (float*)(sm + SM_B0);
    const uint32_t smb = smem_u32(sm);

    const int tid = threadIdx.x, w = tid >> 5, lane = tid & 31;
    const int wm = w & 3, wn = w >> 2;       /* warp grid 4m x 4n */
    const int g = lane >> 2, qi = lane & 3;
    const long base = (long)blockIdx.x * MTILE;

    /* ldmatrix lane geometry */
    const int atj = lane >> 3;
    const int a_row = (atj & 1)*8 + (lane & 7);
    const int a_cc  = atj >> 1;
    /* x4-trans B geometry: mats 0/1 rows k..k+15 col n0; mats 2/3 same rows col n0+8 */
    const int b4_row = (lane & 7) + ((lane >> 3) & 1) * 8;
    const uint32_t b4_co = (uint32_t)(lane >> 4) * 16;

    const int arow0 = 32*wm + a_row;
    const int arow1 = arow0 + 16;
    const uint32_t rbA0 = smb + (uint32_t)arow0*XSTR + (uint32_t)a_cc*16;
    const uint32_t rbA1 = smb + (uint32_t)arow1*XSTR + (uint32_t)a_cc*16;

    for (int i = tid; i < 768; i += NTHR) w0s[i] = w0g[i];
    for (int i = tid; i < 256; i += NTHR) b0s[i] = b0g[i];
    issue_chunk(0, smb, tid);
    issue_chunk(1, smb, tid);
    __syncthreads();   /* w0s/b0s staging must complete before layer-0 reads */

    /* ---- layer 0: x = sin(5*(pos @ W0 + b0)) -> SMEM bf16 hi/mid ---- */
    {
        int r = tid >> 2, q = tid & 3;       /* 512 thr: 128 rows x 4 col-quarters */
        float p0 = pos[(base + r)*3], p1 = pos[(base + r)*3 + 1], p2 = pos[(base + r)*3 + 2];
        const uint32_t rb = (uint32_t)r*XSTR;
#pragma unroll
        for (int c = 0; c < 64; c += 2) {
            int c0 = q*64 + c;
            float h0 = fmaf(p0, w0s[c0],   fmaf(p1, w0s[256+c0],   fmaf(p2, w0s[512+c0],   b0s[c0])));
            float h1 = fmaf(p0, w0s[c0+1], fmaf(p1, w0s[256+c0+1], fmaf(p2, w0s[512+c0+1], b0s[c0+1])));
            float v0 = __sinf(5.0f*h0), v1 = __sinf(5.0f*h1);
            uint32_t hp, mp; split2(v0, v1, hp, mp);
            uint32_t off = rb + (uint32_t)c0*2;
            *(uint32_t*)(sm + SM_XHI + off) = hp;
            *(uint32_t*)(sm + SM_XLO + off) = mp;
        }
    }

    float oacc[2][2][4];
#pragma unroll
    for (int a = 0; a < 2; ++a)
#pragma unroll
        for (int b = 0; b < 2; ++b)
#pragma unroll
            for (int q = 0; q < 4; ++q) oacc[a][b][q] = 0.f;

    int cc = 0;

    for (int l = 0; l < GL; ++l) {
        __syncthreads();
        {
            float gsc = 6.283185307179586f * (float)(1 << l);
            for (int i = tid; i < 2048; i += NTHR) ffnS[i] = ffnA[l*2048 + i] * gsc;
            for (int i = tid; i < 256;  i += NTHR) bhs[i]  = 5.0f * bhv[l*256 + i];
            for (int i = tid; i < 64;   i += NTHR) bhhs[i] = 5.0f * bhhg[l*64 + i];
        }

        float acc[2][8][4];
#pragma unroll
        for (int mt = 0; mt < 2; ++mt)
#pragma unroll
            for (int nt = 0; nt < 8; ++nt)
#pragma unroll
                for (int q = 0; q < 4; ++q) acc[mt][nt][q] = 0.f;

        /* ---- main GEMM (3-term): pass0 = Wm x Ah; pass1 = Wh x (Ah+Am) ---- */
#pragma unroll
        for (int pass = 0; pass < 2; ++pass) {
            for (int kc = 0; kc < 4; ++kc) {
                if (cc + 1 < NCHUNK_T) asm volatile("cp.async.wait_group 1;" ::: "memory");
                else                   asm volatile("cp.async.wait_group 0;" ::: "memory");
                __syncthreads();
                const uint32_t slot = smb + SM_WR + (uint32_t)(cc & 1)*CHUNKB;
                for (int ks = 0; ks < 4; ++ks) {
                    const int k = kc*64 + ks*16;
                    const uint32_t koff = (uint32_t)(k >> 3) * 16;
                    uint32_t ah0[4], ah1[4], am0[4], am1[4];
                    ldA(ah0, rbA0 + SM_XHI + koff);
                    ldA(ah1, rbA1 + SM_XHI + koff);
                    if (pass == 1) {
                        ldA(am0, rbA0 + SM_XLO + koff);
                        ldA(am1, rbA1 + SM_XLO + koff);
                    }
                    const uint32_t brow4 = slot + (uint32_t)(ks*16 + b4_row)*WSTR
                                         + (uint32_t)wn*128 + b4_co;
                    uint32_t bb[4][4];
#pragma unroll
                    for (int np = 0; np < 4; ++np)
                        ldBt4(bb[np], brow4 + (uint32_t)np*32);
#pragma unroll
                    for (int np = 0; np < 4; ++np) {
                        mma_bf16(acc[0][2*np  ], ah0, bb[np]);
                        mma_bf16(acc[0][2*np+1], ah0, bb[np]+2);
                        mma_bf16(acc[1][2*np  ], ah1, bb[np]);
                        mma_bf16(acc[1][2*np+1], ah1, bb[np]+2);
                        if (pass == 1) {
                            mma_bf16(acc[0][2*np  ], am0, bb[np]);
                            mma_bf16(acc[0][2*np+1], am0, bb[np]+2);
                            mma_bf16(acc[1][2*np  ], am1, bb[np]);
                            mma_bf16(acc[1][2*np+1], am1, bb[np]+2);
                        }
                    }
                }
                __syncthreads();
                if (cc + 2 < NCHUNK_T) issue_chunk(cc + 2, smb, tid);
                ++cc;
            }
        }

        /* ---- epilogue: x_new = sin(5*D + 5*bh) + sin(gf @ ffnS) ---- */
#pragma unroll
        for (int mt = 0; mt < 2; ++mt) {
            const int r0 = 32*wm + 16*mt + g;
            float gfa[2][8];
#pragma unroll
            for (int p = 0; p < 2; ++p) {
                const float* gp = gf + (base + r0 + 8*p)*40 + l*8;
                float4 u = *(const float4*)gp, v2 = *(const float4*)(gp + 4);
                gfa[p][0]=u.x; gfa[p][1]=u.y; gfa[p][2]=u.z; gfa[p][3]=u.w;
                gfa[p][4]=v2.x; gfa[p][5]=v2.y; gfa[p][6]=v2.z; gfa[p][7]=v2.w;
            }
#pragma unroll
            for (int nt = 0; nt < 8; ++nt) {
                const int n0 = 64*wn + 8*nt + 2*qi;
                float rs00=0.f, rs01=0.f, rs10=0.f, rs11=0.f;
#pragma unroll
                for (int f = 0; f < 8; ++f) {
                    float2 fp = *(const float2*)&ffnS[f*256 + n0];
                    rs00 = fmaf(gfa[0][f], fp.x, rs00);
                    rs01 = fmaf(gfa[0][f], fp.y, rs01);
                    rs10 = fmaf(gfa[1][f], fp.x, rs10);
                    rs11 = fmaf(gfa[1][f], fp.y, rs11);
                }
                const float bh0 = bhs[n0], bh1 = bhs[n0+1];
                float v00 = __sinf(fmaf(acc[mt][nt][0], 5.0f, bh0)) + __sinf(rs00);
                float v01 = __sinf(fmaf(acc[mt][nt][1], 5.0f, bh1)) + __sinf(rs01);
                float v10 = __sinf(fmaf(acc[mt][nt][2], 5.0f, bh0)) + __sinf(rs10);
                float v11 = __sinf(fmaf(acc[mt][nt][3], 5.0f, bh1)) + __sinf(rs11);
                uint32_t hp, mp;
                split2(v00, v01, hp, mp);
                uint32_t off = (uint32_t)r0*XSTR + (uint32_t)n0*2;
                *(uint32_t*)(sm + SM_XHI + off) = hp;
                *(uint32_t*)(sm + SM_XLO + off) = mp;
                split2(v10, v11, hp, mp);
                off = (uint32_t)(r0+8)*XSTR + (uint32_t)n0*2;
                *(uint32_t*)(sm + SM_XHI + off) = hp;
                *(uint32_t*)(sm + SM_XLO + off) = mp;
            }
        }

        /* ---- head GEMM (3-term): pass0 = Hm x Ah; pass1 = Hh x (Ah+Am) ---- */
        float acc2[2][2][4];
#pragma unroll
        for (int mt = 0; mt < 2; ++mt)
#pragma unroll
            for (int nt = 0; nt < 2; ++nt)
#pragma unroll
                for (int q = 0; q < 4; ++q) acc2[mt][nt][q] = 0.f;

#pragma unroll
        for (int pass = 0; pass < 2; ++pass) {
            if (cc + 1 < NCHUNK_T) asm volatile("cp.async.wait_group 1;" ::: "memory");
            else                   asm volatile("cp.async.wait_group 0;" ::: "memory");
            __syncthreads();
            const uint32_t slot = smb + SM_WR + (uint32_t)(cc & 1)*CHUNKB;
            for (int ks = 0; ks < 16; ++ks) {
                const int k = ks*16;
                const uint32_t koff = (uint32_t)(k >> 3) * 16;
                uint32_t ah0[4], ah1[4], am0[4], am1[4];
                ldA(ah0, rbA0 + SM_XHI + koff);
                ldA(ah1, rbA1 + SM_XHI + koff);
                if (pass == 1) {
                    ldA(am0, rbA0 + SM_XLO + koff);
                    ldA(am1, rbA1 + SM_XLO + koff);
                }
                uint32_t bb[4];
                ldBt4(bb, slot + (uint32_t)(k + b4_row)*HSTR + (uint32_t)wn*32 + b4_co);
                mma_bf16(acc2[0][0], ah0, bb);
                mma_bf16(acc2[0][1], ah0, bb+2);
                mma_bf16(acc2[1][0], ah1, bb);
                mma_bf16(acc2[1][1], ah1, bb+2);
                if (pass == 1) {
                    mma_bf16(acc2[0][0], am0, bb);
                    mma_bf16(acc2[0][1], am0, bb+2);
                    mma_bf16(acc2[1][0], am1, bb);
                    mma_bf16(acc2[1][1], am1, bb+2);
                }
            }
            __syncthreads();
            if (cc + 2 < NCHUNK_T) issue_chunk(cc + 2, smb, tid);
            ++cc;
        }

        /* ---- head epilogue: out += sin(5*D2 + 5*bhh) ---- */
#pragma unroll
        for (int mt = 0; mt < 2; ++mt)
#pragma unroll
            for (int nt = 0; nt < 2; ++nt) {
                const int n0 = 16*wn + 8*nt + 2*qi;
                const float bh0 = bhhs[n0], bh1 = bhhs[n0+1];
                oacc[mt][nt][0] += __sinf(fmaf(acc2[mt][nt][0], 5.0f, bh0));
                oacc[mt][nt][1] += __sinf(fmaf(acc2[mt][nt][1], 5.0f, bh1));
                oacc[mt][nt][2] += __sinf(fmaf(acc2[mt][nt][2], 5.0f, bh0));
                oacc[mt][nt][3] += __sinf(fmaf(acc2[mt][nt][3], 5.0f, bh1));
            }
    }

    /* ---- output ---- */
#pragma unroll
    for (int mt = 0; mt < 2; ++mt)
#pragma unroll
        for (int p = 0; p < 2; ++p) {
            const long row = base + 32*wm + 16*mt + g + 8*p;
#pragma unroll
            for (int nt = 0; nt < 2; ++nt) {
                const int n0 = 16*wn + 8*nt + 2*qi;
                float2 v;
                v.x = oacc[mt][nt][2*p];
                v.y = oacc[mt][nt][2*p + 1];
                *(float2*)(outp + row*(long)OD + n0) = v;
            }
        }
}

extern "C" void kernel_launch(void* const* d_in, const int* in_sizes, int n_in,
                              void* d_out, int out_size) {
    const float *pos=0,*gfp=0,*ffn=0,*w0=0,*b0=0,*wh=0,*bh=0,*whh=0,*bhh=0;
    for (int i = 0; i < n_in; ++i) {
        const float* p = (const float*)d_in[i];
        switch (in_sizes[i]) {
            case NPTS*3:      pos = p; break;
            case NPTS*GL*8:   gfp = p; break;
            case GL*8*WD:     ffn = p; break;
            case 3*WD:        w0  = p; break;
            case WD:          b0  = p; break;
            case GL*WD*WD:    wh  = p; break;
            case GL*WD:       bh  = p; break;
            case GL*WD*OD:    whh = p; break;
            case GL*OD:       bhh = p; break;
        }
    }
    prep_kernel<<<(GL*WD*WD + GL*WD*OD)/256, 256>>>(wh, whh);
    cudaFuncSetAttribute(ffb_mma, cudaFuncAttributeMaxDynamicSharedMemorySize, SMEM_BYTES);
    ffb_mma<<<NPTS/MTILE, NTHR, SMEM_BYTES>>>(pos, gfp, ffn, w0, b0, bh, bhh, (float*)d_out);
}

// round 13
// speedup vs baseline: 1.7211x; 1.0623x over previous
#include <cuda_runtime.h>
#include <cuda_bf16.h>
#include <cstdint>

#define NPTS 131072
#define GL 5
#define WD 256
#define OD 64
#define MTILE 128
#define NTHR 256
#define CHUNKB 36864       /* uniform padded chunk: 256 thr x 144B */
#define NCHUNK_T 50        /* 10/layer: 4 Wm, 4 Wh, 1 Hm, 1 Hh */

#define XSTR 528           /* x row stride bytes (512 data + 16 pad) */
#define WSTR 528           /* main W row stride */
#define HSTR 144           /* head W row stride (128 data + 16 pad) */

/* pre-split weights, padded-stride layout: [0]=mid residual, [1]=hi */
__device__ __align__(1024) unsigned char g_wm[2][GL][4][CHUNKB];
__device__ __align__(1024) unsigned char g_wh[2][GL][CHUNKB];

/* ---- shared memory byte offsets ---- */
#define SM_XHI 0                 /* 128 rows x 528B */
#define SM_XLO 67584
#define SM_WR  135168            /* ring: 2 x 36864 */
#define SM_FFN 208896            /* 8 x 256 f32 */
#define SM_BH  217088            /* 5*bh: 256 f32 */
#define SM_BHH 218112            /* 5*bhh: 64 f32 */
#define SM_W0  218368            /* 3 x 256 f32 */
#define SM_B0  221440            /* 256 f32 */
#define SMEM_BYTES 222464

__device__ __forceinline__ uint32_t smem_u32(const void* p) {
    uint32_t a;
    asm("{ .reg .u64 t; cvta.to.shared.u64 t, %1; cvt.u32.u64 %0, t; }" : "=r"(a) : "l"(p));
    return a;
}

__device__ __forceinline__ void ldA(uint32_t* a, uint32_t addr) {
    asm volatile("ldmatrix.sync.aligned.m8n8.x4.shared.b16 {%0,%1,%2,%3}, [%4];"
        : "=r"(a[0]),"=r"(a[1]),"=r"(a[2]),"=r"(a[3]) : "r"(addr));
}
/* x4 trans: mats 0/1 = rows k..k+15 @ col n0, mats 2/3 = same rows @ col n0+8 */
__device__ __forceinline__ void ldBt4(uint32_t* b, uint32_t addr) {
    asm volatile("ldmatrix.sync.aligned.m8n8.x4.trans.shared.b16 {%0,%1,%2,%3}, [%4];"
        : "=r"(b[0]),"=r"(b[1]),"=r"(b[2]),"=r"(b[3]) : "r"(addr));
}
__device__ __forceinline__ void mma_bf16(float* c, const uint32_t* a, const uint32_t* b) {
    asm volatile("mma.sync.aligned.m16n8k16.row.col.f32.bf16.bf16.f32 "
        "{%0,%1,%2,%3},{%4,%5,%6,%7},{%8,%9},{%0,%1,%2,%3};"
        : "+f"(c[0]),"+f"(c[1]),"+f"(c[2]),"+f"(c[3])
        : "r"(a[0]),"r"(a[1]),"r"(a[2]),"r"(a[3]), "r"(b[0]),"r"(b[1]));
}

/* (v0,v1) -> bf16x2 hi word + bf16x2 residual word (unscaled) */
__device__ __forceinline__ void split2(float v0, float v1, uint32_t& hp, uint32_t& mp) {
    asm("cvt.rn.bf16x2.f32 %0, %1, %2;" : "=r"(hp) : "f"(v1), "f"(v0));
    float h0 = __uint_as_float(hp << 16);
    float h1 = __uint_as_float(hp & 0xffff0000u);
    asm("cvt.rn.bf16x2.f32 %0, %1, %2;" : "=r"(mp) : "f"(v1 - h1), "f"(v0 - h0));
}

__device__ __forceinline__ const unsigned char* chunk_ptr(int c) {
    int l = c / 10, j = c - l * 10;
    if (j < 4) return g_wm[0][l][j];        /* Wm */
    if (j < 8) return g_wm[1][l][j - 4];    /* Wh */
    return g_wh[j - 8][l];                  /* Hm, Hh */
}

__device__ __forceinline__ void issue_chunk(int c, uint32_t smb, int tid) {
    const unsigned char* src = chunk_ptr(c) + tid * 144;
    uint32_t dst = smb + SM_WR + (uint32_t)(c & 1) * CHUNKB + (uint32_t)tid * 144;
#pragma unroll
    for (int i = 0; i < 9; ++i)
        asm volatile("cp.async.cg.shared.global [%0], [%1], 16;"
            :: "r"(dst + i*16), "l"(src + i*16) : "memory");
    asm volatile("cp.async.commit_group;" ::: "memory");
}

/* ---------- prep: bf16 2-term split into padded-stride layout ---------- */
__global__ void prep_kernel(const float* __restrict__ wh, const float* __restrict__ whh) {
    int idx = blockIdx.x * blockDim.x + threadIdx.x;
    if (idx < GL*WD*WD) {
        int l = idx >> 16, r = idx & 65535, k = r >> 8, n = r & 255;
        float wv = wh[idx];
        __nv_bfloat16 h = __float2bfloat16(wv);
        __nv_bfloat16 m = __float2bfloat16(wv - __bfloat162float(h));
        int kc = k >> 6, kk = k & 63;
        uint32_t off = (uint32_t)kk*WSTR + (uint32_t)n*2;
        *(__nv_bfloat16*)&g_wm[1][l][kc][off] = h;
        *(__nv_bfloat16*)&g_wm[0][l][kc][off] = m;
    } else {
        int j = idx - GL*WD*WD;
        if (j < GL*WD*OD) {
            int l = j / (WD*OD), r = j % (WD*OD), k = r >> 6, o = r & 63;
            float wv = whh[j];
            __nv_bfloat16 h = __float2bfloat16(wv);
            __nv_bfloat16 m = __float2bfloat16(wv - __bfloat162float(h));
            uint32_t off = (uint32_t)k*HSTR + (uint32_t)o*2;
            *(__nv_bfloat16*)&g_wh[1][l][off] = h;
            *(__nv_bfloat16*)&g_wh[0][l][off] = m;
        }
    }
}

/* ---------- main fused kernel: 256 thr, warp grid 4m x 2n, 3-term split ---------- */
__global__ void __launch_bounds__(NTHR, 1)
ffb_mma(const float* __restrict__ pos, const float* __restrict__ gf,
        const float* __restrict__ ffnA, const float* __restrict__ w0g,
        const float* __restrict__ b0g, const float* __restrict__ bhv,
        const float* __restrict__ bhhg, float* __restrict__ outp)
{
    extern __shared__ __align__(1024) unsigned char sm[];
    float* ffnS = (float*)(sm + SM_FFN);
    float* bhs  = (float*)(sm + SM_BH);
    float* bhhs = (float*)(sm + SM_BHH);
    float* w0s  = (float*)(sm + SM_W0);
    float* b0s  = (float*)(sm + SM_B0);
    const uint32_t smb = smem_u32(sm);

    const int tid = threadIdx.x, w = tid >> 5, lane = tid & 31;
    const int wm = w & 3, wn = w >> 2;       /* warp grid 4m x 2n */
    const int g = lane >> 2, qi = lane & 3;
    const long base = (long)blockIdx.x * MTILE;

    /* ldmatrix lane geometry */
    const int atj = lane >> 3;
    const int a_row = (atj & 1)*8 + (lane & 7);
    const int a_cc  = atj >> 1;
    const int b4_row = (lane & 7) + ((lane >> 3) & 1) * 8;
    const uint32_t b4_co = (uint32_t)(lane >> 4) * 16;

    const int arow0 = 32*wm + a_row;
    const int arow1 = arow0 + 16;
    const uint32_t rbA0 = smb + (uint32_t)arow0*XSTR + (uint32_t)a_cc*16;
    const uint32_t rbA1 = smb + (uint32_t)arow1*XSTR + (uint32_t)a_cc*16;

    for (int i = tid; i < 768; i += NTHR) w0s[i] = w0g[i];
    for (int i = tid; i < 256; i += NTHR) b0s[i] = b0g[i];
    issue_chunk(0, smb, tid);
    issue_chunk(1, smb, tid);
    __syncthreads();   /* w0s/b0s staging must complete before layer-0 reads */

    /* ---- layer 0: x = sin(5*(pos @ W0 + b0)) -> SMEM bf16 hi/mid ---- */
    {
        int r = tid >> 1, hh = tid & 1;
        float p0 = pos[(base + r)*3], p1 = pos[(base + r)*3 + 1], p2 = pos[(base + r)*3 + 2];
        const uint32_t rb = (uint32_t)r*XSTR;
#pragma unroll
        for (int c = 0; c < 128; c += 2) {
            int c0 = hh*128 + c;
            float h0 = fmaf(p0, w0s[c0],   fmaf(p1, w0s[256+c0],   fmaf(p2, w0s[512+c0],   b0s[c0])));
            float h1 = fmaf(p0, w0s[c0+1], fmaf(p1, w0s[256+c0+1], fmaf(p2, w0s[512+c0+1], b0s[c0+1])));
            float v0 = __sinf(5.0f*h0), v1 = __sinf(5.0f*h1);
            uint32_t hp, mp; split2(v0, v1, hp, mp);
            uint32_t off = rb + (uint32_t)c0*2;
            *(uint32_t*)(sm + SM_XHI + off) = hp;
            *(uint32_t*)(sm + SM_XLO + off) = mp;
        }
    }

    float oacc[2][4][4];
#pragma unroll
    for (int a = 0; a < 2; ++a)
#pragma unroll
        for (int b = 0; b < 4; ++b)
#pragma unroll
            for (int q = 0; q < 4; ++q) oacc[a][b][q] = 0.f;

    int cc = 0;

    for (int l = 0; l < GL; ++l) {
        __syncthreads();
        {
            float gsc = 6.283185307179586f * (float)(1 << l);
            for (int i = tid; i < 2048; i += NTHR) ffnS[i] = ffnA[l*2048 + i] * gsc;
            for (int i = tid; i < 256;  i += NTHR) bhs[i]  = 5.0f * bhv[l*256 + i];
            for (int i = tid; i < 64;   i += NTHR) bhhs[i] = 5.0f * bhhg[l*64 + i];
        }

        float acc[2][16][4];
#pragma unroll
        for (int mt = 0; mt < 2; ++mt)
#pragma unroll
            for (int nt = 0; nt < 16; ++nt)
#pragma unroll
                for (int q = 0; q < 4; ++q) acc[mt][nt][q] = 0.f;

        /* ---- main GEMM (3-term): pass0 = Wm x Ah; pass1 = Wh x (Ah+Am) ---- */
#pragma unroll
        for (int pass = 0; pass < 2; ++pass) {
            for (int kc = 0; kc < 4; ++kc) {
                if (cc + 1 < NCHUNK_T) asm volatile("cp.async.wait_group 1;" ::: "memory");
                else                   asm volatile("cp.async.wait_group 0;" ::: "memory");
                __syncthreads();
                const uint32_t slot = smb + SM_WR + (uint32_t)(cc & 1)*CHUNKB;
                for (int ks = 0; ks < 4; ++ks) {
                    const int k = kc*64 + ks*16;
                    const uint32_t koff = (uint32_t)(k >> 3) * 16;
                    uint32_t ah0[4], ah1[4], am0[4], am1[4];
                    ldA(ah0, rbA0 + SM_XHI + koff);
                    ldA(ah1, rbA1 + SM_XHI + koff);
                    if (pass == 1) {
                        ldA(am0, rbA0 + SM_XLO + koff);
                        ldA(am1, rbA1 + SM_XLO + koff);
                    }
                    const uint32_t brow4 = slot + (uint32_t)(ks*16 + b4_row)*WSTR
                                         + (uint32_t)wn*256 + b4_co;
#pragma unroll
                    for (int np = 0; np < 8; ++np) {
                        uint32_t bb[4];
                        ldBt4(bb, brow4 + (uint32_t)np*32);
                        mma_bf16(acc[0][2*np  ], ah0, bb);
                        mma_bf16(acc[0][2*np+1], ah0, bb+2);
                        mma_bf16(acc[1][2*np  ], ah1, bb);
                        mma_bf16(acc[1][2*np+1], ah1, bb+2);
                        if (pass == 1) {
                            mma_bf16(acc[0][2*np  ], am0, bb);
                            mma_bf16(acc[0][2*np+1], am0, bb+2);
                            mma_bf16(acc[1][2*np  ], am1, bb);
                            mma_bf16(acc[1][2*np+1], am1, bb+2);
                        }
                    }
                }
                __syncthreads();
                if (cc + 2 < NCHUNK_T) issue_chunk(cc + 2, smb, tid);
                ++cc;
            }
        }

        /* ---- epilogue: x_new = sin(5*D + 5*bh) + sin(gf @ ffnS) ---- */
#pragma unroll
        for (int mt = 0; mt < 2; ++mt) {
            const int r0 = 32*wm + 16*mt + g;
            float gfa[2][8];
#pragma unroll
            for (int p = 0; p < 2; ++p) {
                const float* gp = gf + (base + r0 + 8*p)*40 + l*8;
                float4 u = *(const float4*)gp, v2 = *(const float4*)(gp + 4);
                gfa[p][0]=u.x; gfa[p][1]=u.y; gfa[p][2]=u.z; gfa[p][3]=u.w;
                gfa[p][4]=v2.x; gfa[p][5]=v2.y; gfa[p][6]=v2.z; gfa[p][7]=v2.w;
            }
#pragma unroll
            for (int nt = 0; nt < 16; ++nt) {
                const int n0 = 128*wn + 8*nt + 2*qi;
                float rs00=0.f, rs01=0.f, rs10=0.f, rs11=0.f;
#pragma unroll
                for (int f = 0; f < 8; ++f) {
                    float2 fp = *(const float2*)&ffnS[f*256 + n0];
                    rs00 = fmaf(gfa[0][f], fp.x, rs00);
                    rs01 = fmaf(gfa[0][f], fp.y, rs01);
                    rs10 = fmaf(gfa[1][f], fp.x, rs10);
                    rs11 = fmaf(gfa[1][f], fp.y, rs11);
                }
                const float bh0 = bhs[n0], bh1 = bhs[n0+1];
                float v00 = __sinf(fmaf(acc[mt][nt][0], 5.0f, bh0)) + __sinf(rs00);
                float v01 = __sinf(fmaf(acc[mt][nt][1], 5.0f, bh1)) + __sinf(rs01);
                float v10 = __sinf(fmaf(acc[mt][nt][2], 5.0f, bh0)) + __sinf(rs10);
                float v11 = __sinf(fmaf(acc[mt][nt][3], 5.0f, bh1)) + __sinf(rs11);
                uint32_t hp, mp;
                split2(v00, v01, hp, mp);
                uint32_t off = (uint32_t)r0*XSTR + (uint32_t)n0*2;
                *(uint32_t*)(sm + SM_XHI + off) = hp;
                *(uint32_t*)(sm + SM_XLO + off) = mp;
                split2(v10, v11, hp, mp);
                off = (uint32_t)(r0+8)*XSTR + (uint32_t)n0*2;
                *(uint32_t*)(sm + SM_XHI + off) = hp;
                *(uint32_t*)(sm + SM_XLO + off) = mp;
            }
        }

        /* ---- head GEMM (3-term): pass0 = Hm x Ah; pass1 = Hh x (Ah+Am) ---- */
        float acc2[2][4][4];
#pragma unroll
        for (int mt = 0; mt < 2; ++mt)
#pragma unroll
            for (int nt = 0; nt < 4; ++nt)
#pragma unroll
                for (int q = 0; q < 4; ++q) acc2[mt][nt][q] = 0.f;

#pragma unroll
        for (int pass = 0; pass < 2; ++pass) {
            if (cc + 1 < NCHUNK_T) asm volatile("cp.async.wait_group 1;" ::: "memory");
            else                   asm volatile("cp.async.wait_group 0;" ::: "memory");
            __syncthreads();
            const uint32_t slot = smb + SM_WR + (uint32_t)(cc & 1)*CHUNKB;
            for (int ks = 0; ks < 16; ++ks) {
                const int k = ks*16;
                const uint32_t koff = (uint32_t)(k >> 3) * 16;
                uint32_t ah0[4], ah1[4], am0[4], am1[4];
                ldA(ah0, rbA0 + SM_XHI + koff);
                ldA(ah1, rbA1 + SM_XHI + koff);
                if (pass == 1) {
                    ldA(am0, rbA0 + SM_XLO + koff);
                    ldA(am1, rbA1 + SM_XLO + koff);
                }
                const uint32_t brow4 = slot + (uint32_t)(k + b4_row)*HSTR
                                     + (uint32_t)wn*64 + b4_co;
#pragma unroll
                for (int np = 0; np < 2; ++np) {
                    uint32_t bb[4];
                    ldBt4(bb, brow4 + (uint32_t)np*32);
                    mma_bf16(acc2[0][2*np  ], ah0, bb);
                    mma_bf16(acc2[0][2*np+1], ah0, bb+2);
                    mma_bf16(acc2[1][2*np  ], ah1, bb);
                    mma_bf16(acc2[1][2*np+1], ah1, bb+2);
                    if (pass == 1) {
                        mma_bf16(acc2[0][2*np  ], am0, bb);
                        mma_bf16(acc2[0][2*np+1], am0, bb+2);
                        mma_bf16(acc2[1][2*np  ], am1, bb);
                        mma_bf16(acc2[1][2*np+1], am1, bb+2);
                    }
                }
            }
            __syncthreads();
            if (cc + 2 < NCHUNK_T) issue_chunk(cc + 2, smb, tid);
            ++cc;
        }

        /* ---- head epilogue: out += sin(5*D2 + 5*bhh) ---- */
#pragma unroll
        for (int mt = 0; mt < 2; ++mt)
#pragma unroll
            for (int nt = 0; nt < 4; ++nt) {
                const int n0 = 32*wn + 8*nt + 2*qi;
                const float bh0 = bhhs[n0], bh1 = bhhs[n0+1];
                oacc[mt][nt][0] += __sinf(fmaf(acc2[mt][nt][0], 5.0f, bh0));
                oacc[mt][nt][1] += __sinf(fmaf(acc2[mt][nt][1], 5.0f, bh1));
                oacc[mt][nt][2] += __sinf(fmaf(acc2[mt][nt][2], 5.0f, bh0));
                oacc[mt][nt][3] += __sinf(fmaf(acc2[mt][nt][3], 5.0f, bh1));
            }
    }

    /* ---- output ---- */
#pragma unroll
    for (int mt = 0; mt < 2; ++mt)
#pragma unroll
        for (int p = 0; p < 2; ++p) {
            const long row = base + 32*wm + 16*mt + g + 8*p;
#pragma unroll
            for (int nt = 0; nt < 4; ++nt) {
                const int n0 = 32*wn + 8*nt + 2*qi;
                float2 v;
                v.x = oacc[mt][nt][2*p];
                v.y = oacc[mt][nt][2*p + 1];
                *(float2*)(outp + row*(long)OD + n0) = v;
            }
        }
}

extern "C" void kernel_launch(void* const* d_in, const int* in_sizes, int n_in,
                              void* d_out, int out_size) {
    const float *pos=0,*gfp=0,*ffn=0,*w0=0,*b0=0,*wh=0,*bh=0,*whh=0,*bhh=0;
    for (int i = 0; i < n_in; ++i) {
        const float* p = (const float*)d_in[i];
        switch (in_sizes[i]) {
            case NPTS*3:      pos = p; break;
            case NPTS*GL*8:   gfp = p; break;
            case GL*8*WD:     ffn = p; break;
            case 3*WD:        w0  = p; break;
            case WD:          b0  = p; break;
            case GL*WD*WD:    wh  = p; break;
            case GL*WD:       bh  = p; break;
            case GL*WD*OD:    whh = p; break;
            case GL*OD:       bhh = p; break;
        }
    }
    prep_kernel<<<(GL*WD*WD + GL*WD*OD)/256, 256>>>(wh, whh);
    cudaFuncSetAttribute(ffb_mma, cudaFuncAttributeMaxDynamicSharedMemorySize, SMEM_BYTES);
    ffb_mma<<<NPTS/MTILE, NTHR, SMEM_BYTES>>>(pos, gfp, ffn, w0, b0, bh, bhh, (float*)d_out);
}

// round 14
// speedup vs baseline: 2.4694x; 1.4348x over previous
#include <cuda_runtime.h>
#include <cuda_bf16.h>
#include <cstdint>

#define NPTS 131072
#define GL 5
#define WD 256
#define OD 64
#define MTILE 128
#define NTHR 256

#define XSTR 528           /* x row stride bytes (512 data + 16 pad) */

/* weights in mma B-fragment order: [term][layer][kstep][ntile][lane] (uint2) */
__device__ __align__(1024) uint2 g_wfm[2][GL][16][32][32];  /* main: 1.31 MB */
__device__ __align__(1024) uint2 g_wfh[2][GL][16][8][32];   /* head: 328 KB  */

/* ---- shared memory byte offsets ---- */
#define SM_XHI 0                 /* 128 rows x 528B */
#define SM_XLO 67584
#define SM_FFN 135168            /* 8 x 256 f32 */
#define SM_BH  143360            /* 5*bh: 256 f32 */
#define SM_BHH 144384            /* 5*bhh: 64 f32 */
#define SM_W0  144640            /* 3 x 256 f32 */
#define SM_B0  147712            /* 256 f32 */
#define SMEM_BYTES 148736

__device__ __forceinline__ uint32_t smem_u32(const void* p) {
    uint32_t a;
    asm("{ .reg .u64 t; cvta.to.shared.u64 t, %1; cvt.u32.u64 %0, t; }" : "=r"(a) : "l"(p));
    return a;
}

__device__ __forceinline__ void ldA(uint32_t* a, uint32_t addr) {
    asm volatile("ldmatrix.sync.aligned.m8n8.x4.shared.b16 {%0,%1,%2,%3}, [%4];"
        : "=r"(a[0]),"=r"(a[1]),"=r"(a[2]),"=r"(a[3]) : "r"(addr));
}
__device__ __forceinline__ void mma_bf16(float* c, const uint32_t* a, const uint32_t* b) {
    asm volatile("mma.sync.aligned.m16n8k16.row.col.f32.bf16.bf16.f32 "
        "{%0,%1,%2,%3},{%4,%5,%6,%7},{%8,%9},{%0,%1,%2,%3};"
        : "+f"(c[0]),"+f"(c[1]),"+f"(c[2]),"+f"(c[3])
        : "r"(a[0]),"r"(a[1]),"r"(a[2]),"r"(a[3]), "r"(b[0]),"r"(b[1]));
}

/* (v0,v1) -> bf16x2 hi word + bf16x2 residual word (unscaled) */
__device__ __forceinline__ void split2(float v0, float v1, uint32_t& hp, uint32_t& mp) {
    asm("cvt.rn.bf16x2.f32 %0, %1, %2;" : "=r"(hp) : "f"(v1), "f"(v0));
    float h0 = __uint_as_float(hp << 16);
    float h1 = __uint_as_float(hp & 0xffff0000u);
    asm("cvt.rn.bf16x2.f32 %0, %1, %2;" : "=r"(mp) : "f"(v1 - h1), "f"(v0 - h0));
}

__device__ __forceinline__ uint32_t bfpack(float v0, float v1, int term) {
    if (term == 1) {
        uint32_t r; asm("cvt.rn.bf16x2.f32 %0, %1, %2;" : "=r"(r) : "f"(v1), "f"(v0));
        return r;
    }
    __nv_bfloat16 h0 = __float2bfloat16(v0), h1 = __float2bfloat16(v1);
    float m0 = v0 - __bfloat162float(h0), m1 = v1 - __bfloat162float(h1);
    uint32_t r; asm("cvt.rn.bf16x2.f32 %0, %1, %2;" : "=r"(r) : "f"(m1), "f"(m0));
    return r;
}

/* ---------- prep: emit weights in mma B-fragment order ----------
   PTX m16n8k16 col B fragment: lane (gid=l>>2, tig=l&3) holds
   b0 = {B[k0+2t][n0+g], B[k0+2t+1][n0+g]}, b1 = same with k0+8.      */
__global__ void prep_kernel(const float* __restrict__ wh, const float* __restrict__ whh) {
    int idx = blockIdx.x * blockDim.x + threadIdx.x;
    const int MAIN_T = 2*GL*16*32*32;     /* 163840 */
    if (idx < MAIN_T) {
        int t = idx / (GL*16*32*32);
        int r = idx % (GL*16*32*32);
        int l = r / (16*32*32);
        int r2 = r % (16*32*32);
        int ks = r2 >> 10, gt = (r2 >> 5) & 31, lane = r2 & 31;
        int gid = lane >> 2, tig = lane & 3;
        int k0 = ks*16, n = gt*8 + gid;
        const float* W = wh + (long)l*WD*WD;
        float v00 = W[(k0 + 2*tig    )*WD + n];
        float v01 = W[(k0 + 2*tig + 1)*WD + n];
        float v10 = W[(k0 + 8 + 2*tig    )*WD + n];
        float v11 = W[(k0 + 8 + 2*tig + 1)*WD + n];
        g_wfm[t][l][ks][gt][lane] = make_uint2(bfpack(v00, v01, t), bfpack(v10, v11, t));
    } else {
        int j = idx - MAIN_T;
        if (j < 2*GL*16*8*32) {
            int t = j / (GL*16*8*32);
            int r = j % (GL*16*8*32);
            int l = r / (16*8*32);
            int r2 = r % (16*8*32);
            int ks = r2 >> 8, gt = (r2 >> 5) & 7, lane = r2 & 31;
            int gid = lane >> 2, tig = lane & 3;
            int k0 = ks*16, o = gt*8 + gid;
            const float* W = whh + (long)l*WD*OD;
            float v00 = W[(k0 + 2*tig    )*OD + o];
            float v01 = W[(k0 + 2*tig + 1)*OD + o];
            float v10 = W[(k0 + 8 + 2*tig    )*OD + o];
            float v11 = W[(k0 + 8 + 2*tig + 1)*OD + o];
            g_wfh[t][l][ks][gt][lane] = make_uint2(bfpack(v00, v01, t), bfpack(v10, v11, t));
        }
    }
}

/* ---------- main fused kernel: 256 thr, warp grid 4m x 2n, 3-term split,
              weights streamed as LDG.64 B-fragments (no SMEM ring) ---------- */
__global__ void __launch_bounds__(NTHR, 1)
ffb_mma(const float* __restrict__ pos, const float* __restrict__ gf,
        const float* __restrict__ ffnA, const float* __restrict__ w0g,
        const float* __restrict__ b0g, const float* __restrict__ bhv,
        const float* __restrict__ bhhg, float* __restrict__ outp)
{
    extern __shared__ __align__(1024) unsigned char sm[];
    float* ffnS = (float*)(sm + SM_FFN);
    float* bhs  = (float*)(sm + SM_BH);
    float* bhhs = (float*)(sm + SM_BHH);
    float* w0s  = (float*)(sm + SM_W0);
    float* b0s  = (float*)(sm + SM_B0);
    const uint32_t smb = smem_u32(sm);

    const int tid = threadIdx.x, w = tid >> 5, lane = tid & 31;
    const int wm = w & 3, wn = w >> 2;       /* warp grid 4m x 2n */
    const int g = lane >> 2, qi = lane & 3;
    const long base = (long)blockIdx.x * MTILE;

    /* ldmatrix A lane geometry */
    const int atj = lane >> 3;
    const int a_row = (atj & 1)*8 + (lane & 7);
    const int a_cc  = atj >> 1;
    const int arow0 = 32*wm + a_row;
    const int arow1 = arow0 + 16;
    const uint32_t rbA0 = smb + (uint32_t)arow0*XSTR + (uint32_t)a_cc*16;
    const uint32_t rbA1 = smb + (uint32_t)arow1*XSTR + (uint32_t)a_cc*16;

    for (int i = tid; i < 768; i += NTHR) w0s[i] = w0g[i];
    for (int i = tid; i < 256; i += NTHR) b0s[i] = b0g[i];
    __syncthreads();   /* w0s/b0s staged before layer-0 reads */

    /* ---- layer 0: x = sin(5*(pos @ W0 + b0)) -> SMEM bf16 hi/mid ---- */
    {
        int r = tid >> 1, hh = tid & 1;
        float p0 = pos[(base + r)*3], p1 = pos[(base + r)*3 + 1], p2 = pos[(base + r)*3 + 2];
        const uint32_t rb = (uint32_t)r*XSTR;
#pragma unroll
        for (int c = 0; c < 128; c += 2) {
            int c0 = hh*128 + c;
            float h0 = fmaf(p0, w0s[c0],   fmaf(p1, w0s[256+c0],   fmaf(p2, w0s[512+c0],   b0s[c0])));
            float h1 = fmaf(p0, w0s[c0+1], fmaf(p1, w0s[256+c0+1], fmaf(p2, w0s[512+c0+1], b0s[c0+1])));
            float v0 = __sinf(5.0f*h0), v1 = __sinf(5.0f*h1);
            uint32_t hp, mp; split2(v0, v1, hp, mp);
            uint32_t off = rb + (uint32_t)c0*2;
            *(uint32_t*)(sm + SM_XHI + off) = hp;
            *(uint32_t*)(sm + SM_XLO + off) = mp;
        }
    }
    __syncthreads();   /* layer-0 x visible to all warps' MMA */

    float oacc[2][4][4];
#pragma unroll
    for (int a = 0; a < 2; ++a)
#pragma unroll
        for (int b = 0; b < 4; ++b)
#pragma unroll
            for (int q = 0; q < 4; ++q) oacc[a][b][q] = 0.f;

    for (int l = 0; l < GL; ++l) {
        /* stage per-layer constants (read only by epilogue; barrier below covers) */
        {
            float gsc = 6.283185307179586f * (float)(1 << l);
            for (int i = tid; i < 2048; i += NTHR) ffnS[i] = ffnA[l*2048 + i] * gsc;
            for (int i = tid; i < 256;  i += NTHR) bhs[i]  = 5.0f * bhv[l*256 + i];
            for (int i = tid; i < 64;   i += NTHR) bhhs[i] = 5.0f * bhhg[l*64 + i];
        }

        float acc[2][16][4];
#pragma unroll
        for (int mt = 0; mt < 2; ++mt)
#pragma unroll
            for (int nt = 0; nt < 16; ++nt)
#pragma unroll
                for (int q = 0; q < 4; ++q) acc[mt][nt][q] = 0.f;

        /* ---- main GEMM (3-term): t0 = Wm x Ah; t1 = Wh x (Ah+Am); no barriers ---- */
#pragma unroll
        for (int t = 0; t < 2; ++t) {
            const uint2* __restrict__ wp = &g_wfm[t][l][0][0][0];
            for (int ks = 0; ks < 16; ++ks) {
                const uint32_t koff = (uint32_t)ks*32;
                uint32_t ah0[4], ah1[4], am0[4], am1[4];
                ldA(ah0, rbA0 + SM_XHI + koff);
                ldA(ah1, rbA1 + SM_XHI + koff);
                if (t == 1) {
                    ldA(am0, rbA0 + SM_XLO + koff);
                    ldA(am1, rbA1 + SM_XLO + koff);
                }
                const uint2* __restrict__ wrow = wp + (ks*32 + wn*16)*32 + lane;
#pragma unroll
                for (int half = 0; half < 2; ++half) {
                    uint2 bv[8];
#pragma unroll
                    for (int j = 0; j < 8; ++j) bv[j] = wrow[(half*8 + j)*32];
#pragma unroll
                    for (int j = 0; j < 8; ++j) {
                        const int nt = half*8 + j;
                        uint32_t bb[2] = {bv[j].x, bv[j].y};
                        mma_bf16(acc[0][nt], ah0, bb);
                        mma_bf16(acc[1][nt], ah1, bb);
                        if (t == 1) {
                            mma_bf16(acc[0][nt], am0, bb);
                            mma_bf16(acc[1][nt], am1, bb);
                        }
                    }
                }
            }
        }
        __syncthreads();   /* all x reads + const staging done before epilogue writes */

        /* ---- epilogue: x_new = sin(5*D + 5*bh) + sin(gf @ ffnS) ---- */
#pragma unroll
        for (int mt = 0; mt < 2; ++mt) {
            const int r0 = 32*wm + 16*mt + g;
            float gfa[2][8];
#pragma unroll
            for (int p = 0; p < 2; ++p) {
                const float* gp = gf + (base + r0 + 8*p)*40 + l*8;
                float4 u = *(const float4*)gp, v2 = *(const float4*)(gp + 4);
                gfa[p][0]=u.x; gfa[p][1]=u.y; gfa[p][2]=u.z; gfa[p][3]=u.w;
                gfa[p][4]=v2.x; gfa[p][5]=v2.y; gfa[p][6]=v2.z; gfa[p][7]=v2.w;
            }
#pragma unroll
            for (int nt = 0; nt < 16; ++nt) {
                const int n0 = 128*wn + 8*nt + 2*qi;
                float rs00=0.f, rs01=0.f, rs10=0.f, rs11=0.f;
#pragma unroll
                for (int f = 0; f < 8; ++f) {
                    float2 fp = *(const float2*)&ffnS[f*256 + n0];
                    rs00 = fmaf(gfa[0][f], fp.x, rs00);
                    rs01 = fmaf(gfa[0][f], fp.y, rs01);
                    rs10 = fmaf(gfa[1][f], fp.x, rs10);
                    rs11 = fmaf(gfa[1][f], fp.y, rs11);
                }
                const float bh0 = bhs[n0], bh1 = bhs[n0+1];
                float v00 = __sinf(fmaf(acc[mt][nt][0], 5.0f, bh0)) + __sinf(rs00);
                float v01 = __sinf(fmaf(acc[mt][nt][1], 5.0f, bh1)) + __sinf(rs01);
                float v10 = __sinf(fmaf(acc[mt][nt][2], 5.0f, bh0)) + __sinf(rs10);
                float v11 = __sinf(fmaf(acc[mt][nt][3], 5.0f, bh1)) + __sinf(rs11);
                uint32_t hp, mp;
                split2(v00, v01, hp, mp);
                uint32_t off = (uint32_t)r0*XSTR + (uint32_t)n0*2;
                *(uint32_t*)(sm + SM_XHI + off) = hp;
                *(uint32_t*)(sm + SM_XLO + off) = mp;
                split2(v10, v11, hp, mp);
                off = (uint32_t)(r0+8)*XSTR + (uint32_t)n0*2;
                *(uint32_t*)(sm + SM_XHI + off) = hp;
                *(uint32_t*)(sm + SM_XLO + off) = mp;
            }
        }
        __syncthreads();   /* x_new visible before head MMA reads */

        /* ---- head GEMM (3-term): t0 = Hm x Ah; t1 = Hh x (Ah+Am) ---- */
        float acc2[2][4][4];
#pragma unroll
        for (int mt = 0; mt < 2; ++mt)
#pragma unroll
            for (int nt = 0; nt < 4; ++nt)
#pragma unroll
                for (int q = 0; q < 4; ++q) acc2[mt][nt][q] = 0.f;

#pragma unroll
        for (int t = 0; t < 2; ++t) {
            const uint2* __restrict__ wp = &g_wfh[t][l][0][0][0];
            for (int ks = 0; ks < 16; ++ks) {
                const uint32_t koff = (uint32_t)ks*32;
                uint32_t ah0[4], ah1[4], am0[4], am1[4];
                ldA(ah0, rbA0 + SM_XHI + koff);
                ldA(ah1, rbA1 + SM_XHI + koff);
                if (t == 1) {
                    ldA(am0, rbA0 + SM_XLO + koff);
                    ldA(am1, rbA1 + SM_XLO + koff);
                }
                const uint2* __restrict__ wrow = wp + (ks*8 + wn*4)*32 + lane;
                uint2 bv[4];
#pragma unroll
                for (int j = 0; j < 4; ++j) bv[j] = wrow[j*32];
#pragma unroll
                for (int j = 0; j < 4; ++j) {
                    uint32_t bb[2] = {bv[j].x, bv[j].y};
                    mma_bf16(acc2[0][j], ah0, bb);
                    mma_bf16(acc2[1][j], ah1, bb);
                    if (t == 1) {
                        mma_bf16(acc2[0][j], am0, bb);
                        mma_bf16(acc2[1][j], am1, bb);
                    }
                }
            }
        }

        /* ---- head epilogue: out += sin(5*D2 + 5*bhh) (registers only) ---- */
#pragma unroll
        for (int mt = 0; mt < 2; ++mt)
#pragma unroll
            for (int nt = 0; nt < 4; ++nt) {
                const int n0 = 32*wn + 8*nt + 2*qi;
                const float bh0 = bhhs[n0], bh1 = bhhs[n0+1];
                oacc[mt][nt][0] += __sinf(fmaf(acc2[mt][nt][0], 5.0f, bh0));
                oacc[mt][nt][1] += __sinf(fmaf(acc2[mt][nt][1], 5.0f, bh1));
                oacc[mt][nt][2] += __sinf(fmaf(acc2[mt][nt][2], 5.0f, bh0));
                oacc[mt][nt][3] += __sinf(fmaf(acc2[mt][nt][3], 5.0f, bh1));
            }
    }

    /* ---- output ---- */
#pragma unroll
    for (int mt = 0; mt < 2; ++mt)
#pragma unroll
        for (int p = 0; p < 2; ++p) {
            const long row = base + 32*wm + 16*mt + g + 8*p;
#pragma unroll
            for (int nt = 0; nt < 4; ++nt) {
                const int n0 = 32*wn + 8*nt + 2*qi;
                float2 v;
                v.x = oacc[mt][nt][2*p];
                v.y = oacc[mt][nt][2*p + 1];
                *(float2*)(outp + row*(long)OD + n0) = v;
            }
        }
}

extern "C" void kernel_launch(void* const* d_in, const int* in_sizes, int n_in,
                              void* d_out, int out_size) {
    const float *pos=0,*gfp=0,*ffn=0,*w0=0,*b0=0,*wh=0,*bh=0,*whh=0,*bhh=0;
    for (int i = 0; i < n_in; ++i) {
        const float* p = (const float*)d_in[i];
        switch (in_sizes[i]) {
            case NPTS*3:      pos = p; break;
            case NPTS*GL*8:   gfp = p; break;
            case GL*8*WD:     ffn = p; break;
            case 3*WD:        w0  = p; break;
            case WD:          b0  = p; break;
            case GL*WD*WD:    wh  = p; break;
            case GL*WD:       bh  = p; break;
            case GL*WD*OD:    whh = p; break;
            case GL*OD:       bhh = p; break;
        }
    }
    prep_kernel<<<800, 256>>>(wh, whh);
    cudaFuncSetAttribute(ffb_mma, cudaFuncAttributeMaxDynamicSharedMemorySize, SMEM_BYTES);
    ffb_mma<<<NPTS/MTILE, NTHR, SMEM_BYTES>>>(pos, gfp, ffn, w0, b0, bh, bhh, (float*)d_out);
}